// round 1
// baseline (speedup 1.0000x reference)
#include <cuda_runtime.h>
#include <cuda_bf16.h>
#include <cstdint>

// Problem constants (fixed shapes)
#define XDIM 362
#define GRID_STRIDE 19
#define MAXB 65536

// ---------------- device scratch (no dynamic allocation allowed) ----------------
__device__ float g_att[MAXB * 8];   // gathered 6 neighbor values per row (padded to 8)
__device__ int   g_idx[MAXB * 8];   // the 6 scatter indices per row (padded to 8)
__device__ int   g_perm[MAXB];      // rows bucketed by action
__device__ int   g_hist[3];
__device__ int   g_slot[3];
__device__ int   g_bases[3];

// ---------------- K0: zero counters (must happen every launch; graph-replayed) ---
__global__ void k0_zero() {
    if (threadIdx.x < 3) {
        g_hist[threadIdx.x] = 0;
        g_slot[threadIdx.x] = 0;
    }
}

__device__ __forceinline__ int clampi(int v) {
    v = v < 1 ? 1 : v;
    return v > (XDIM - 1) ? (XDIM - 1) : v;
}

// ---------------- K1: copy x->out, argmax, gather att, idxs, histogram ----------
// one warp per row; 8 warps per block
__global__ void k1_prep(const float* __restrict__ x, const int* __restrict__ act,
                        float* __restrict__ out, int B) {
    __shared__ int s_hist[3];
    if (threadIdx.x < 3) s_hist[threadIdx.x] = 0;
    __syncthreads();

    int warp = (blockIdx.x * blockDim.x + threadIdx.x) >> 5;
    int lane = threadIdx.x & 31;

    if (warp < B) {
        const float* xr = x + (size_t)warp * XDIM;
        float* outr = out + (size_t)warp * XDIM;

        float best = -3.402823466e+38f;
        int bidx = 0;
        // ascending i per lane -> per-lane first max with strict >
        for (int i = lane; i < XDIM; i += 32) {
            float v = xr[i];
            outr[i] = v;
            if (v > best) { best = v; bidx = i; }
        }
        // warp argmax, ties -> smaller index (first occurrence)
        #pragma unroll
        for (int off = 16; off; off >>= 1) {
            float ov = __shfl_xor_sync(0xffffffffu, best, off);
            int   oi = __shfl_xor_sync(0xffffffffu, bidx, off);
            if (ov > best || (ov == best && oi < bidx)) { best = ov; bidx = oi; }
        }
        if (lane == 0) {
            int ptr = bidx;
            int id[6];
            id[0] = 0;
            id[1] = ptr;                        // unclamped, as in source
            id[2] = clampi(ptr - GRID_STRIDE);
            id[3] = clampi(ptr + GRID_STRIDE);
            id[4] = clampi(ptr - 1);
            id[5] = clampi(ptr + 1);
            #pragma unroll
            for (int j = 0; j < 6; j++) {
                g_idx[warp * 8 + j] = id[j];
                g_att[warp * 8 + j] = xr[id[j]];
            }
            atomicAdd(&s_hist[act[warp]], 1);
        }
    }
    __syncthreads();
    if (threadIdx.x < 3) atomicAdd(&g_hist[threadIdx.x], s_hist[threadIdx.x]);
}

// ---------------- K2: exclusive prefix over 3 buckets ---------------------------
__global__ void k2_bases() {
    g_bases[0] = 0;
    g_bases[1] = g_hist[0];
    g_bases[2] = g_hist[0] + g_hist[1];
}

// ---------------- K3: bucket assignment with warp-aggregated atomics ------------
__global__ void k3_assign(const int* __restrict__ act, int B) {
    int i = blockIdx.x * blockDim.x + threadIdx.x;
    int lane = threadIdx.x & 31;
    int a = (i < B) ? act[i] : -1;
    #pragma unroll
    for (int aa = 0; aa < 3; aa++) {
        unsigned m = __ballot_sync(0xffffffffu, a == aa);
        if (a == aa) {
            int leader = __ffs(m) - 1;
            int base = 0;
            if (lane == leader) base = atomicAdd(&g_slot[aa], __popc(m));
            base = __shfl_sync(m, base, leader);
            int off = __popc(m & ((1u << lane) - 1u));
            g_perm[g_bases[aa] + base + off] = i;
        }
    }
}

// ---------------- K4: fused MLP (32 rows/block) + scatter -----------------------
// smem layout sizes
#define H1_STRIDE 101   // 100 padded -> (101*r+k)%32 = (5r+k)%32 conflict-free
#define H2_STRIDE 405   // 400 padded -> (405*r+k)%32 = (21r+k)%32 conflict-free
#define H3_STRIDE 101
#define SMEM_F ((32*H1_STRIDE) + (32*H2_STRIDE) + (32*H3_STRIDE) + (32*8) + (32*6))
#define SMEM_I ((32*8) + 32 + 32)
#define SMEM_BYTES (SMEM_F*4 + SMEM_I*4)

__global__ void __launch_bounds__(256, 2)
k4_mlp(const float* __restrict__ W1, const float* __restrict__ b1,
       const float* __restrict__ W2, const float* __restrict__ b2,
       const float* __restrict__ W3, const float* __restrict__ b3,
       const float* __restrict__ W4, const float* __restrict__ b4,
       const int* __restrict__ actv, float* __restrict__ out, int B) {
    extern __shared__ float sm[];
    float* s_h1   = sm;
    float* s_h2   = s_h1 + 32 * H1_STRIDE;
    float* s_h3   = s_h2 + 32 * H2_STRIDE;
    float* s_att  = s_h3 + 32 * H3_STRIDE;   // 32*8
    float* s_pred = s_att + 32 * 8;          // 32*6
    int*   s_idx  = (int*)(s_pred + 32 * 6); // 32*8
    int*   s_row  = s_idx + 32 * 8;
    int*   s_act  = s_row + 32;

    const int t = threadIdx.x;
    const int gbase = blockIdx.x * 32;

    if (t < 32) {
        int g = gbase + t;
        int row = (g < B) ? g_perm[g] : 0;
        s_row[t] = row;
        s_act[t] = actv[row];
        #pragma unroll
        for (int j = 0; j < 8; j++) {
            s_att[t * 8 + j] = g_att[row * 8 + j];
            s_idx[t * 8 + j] = g_idx[row * 8 + j];
        }
    }
    __syncthreads();

    const int r  = t & 31;   // each thread owns one row of the tile
    const int wg = t >> 5;   // 0..7 (col-group phase)
    const int a  = s_act[r];

    // ---- layer 1: att[6] -> h1[100], relu ----
    {
        const float* w  = W1 + a * 600;   // [6,100]
        const float* bb = b1 + a * 100;
        for (int ng = wg; ng < 25; ng += 8) {
            int n = ng * 4;
            float4 acc = *(const float4*)(bb + n);
            #pragma unroll
            for (int k = 0; k < 6; k++) {
                float  av = s_att[r * 8 + k];
                float4 wv = *(const float4*)(w + k * 100 + n);
                acc.x += av * wv.x; acc.y += av * wv.y;
                acc.z += av * wv.z; acc.w += av * wv.w;
            }
            float* dst = s_h1 + r * H1_STRIDE + n;
            dst[0] = fmaxf(acc.x, 0.f); dst[1] = fmaxf(acc.y, 0.f);
            dst[2] = fmaxf(acc.z, 0.f); dst[3] = fmaxf(acc.w, 0.f);
        }
    }
    __syncthreads();

    // ---- layer 2: h1[100] -> h2[400], relu ----
    {
        const float* w  = W2 + a * 40000; // [100,400]
        const float* bb = b2 + a * 400;
        const float* hr = s_h1 + r * H1_STRIDE;
        for (int ng = wg; ng < 100; ng += 8) {
            int n = ng * 4;
            float4 acc = *(const float4*)(bb + n);
            #pragma unroll 4
            for (int k = 0; k < 100; k++) {
                float  av = hr[k];                           // LDS, conflict-free
                float4 wv = *(const float4*)(w + k * 400 + n); // warp-uniform LDG.128
                acc.x += av * wv.x; acc.y += av * wv.y;
                acc.z += av * wv.z; acc.w += av * wv.w;
            }
            float* dst = s_h2 + r * H2_STRIDE + n;
            dst[0] = fmaxf(acc.x, 0.f); dst[1] = fmaxf(acc.y, 0.f);
            dst[2] = fmaxf(acc.z, 0.f); dst[3] = fmaxf(acc.w, 0.f);
        }
    }
    __syncthreads();

    // ---- layer 3: h2[400] -> h3[100], relu ----
    {
        const float* w  = W3 + a * 40000; // [400,100]
        const float* bb = b3 + a * 100;
        const float* hr = s_h2 + r * H2_STRIDE;
        for (int ng = wg; ng < 25; ng += 8) {
            int n = ng * 4;
            float4 acc = *(const float4*)(bb + n);
            #pragma unroll 4
            for (int k = 0; k < 400; k++) {
                float  av = hr[k];
                float4 wv = *(const float4*)(w + k * 100 + n);
                acc.x += av * wv.x; acc.y += av * wv.y;
                acc.z += av * wv.z; acc.w += av * wv.w;
            }
            float* dst = s_h3 + r * H3_STRIDE + n;
            dst[0] = fmaxf(acc.x, 0.f); dst[1] = fmaxf(acc.y, 0.f);
            dst[2] = fmaxf(acc.z, 0.f); dst[3] = fmaxf(acc.w, 0.f);
        }
    }
    __syncthreads();

    // ---- layer 4: h3[100] -> pred[6] (no relu) ----
    if (t < 192) {
        int rr = t & 31;
        int c  = t >> 5;                  // 0..5
        int aa = s_act[rr];
        const float* w   = W4 + aa * 600; // [100,6]
        const float* hr3 = s_h3 + rr * H3_STRIDE;
        float acc = b4[aa * 6 + c];
        #pragma unroll 4
        for (int k = 0; k < 100; k++) acc += hr3[k] * w[k * 6 + c];
        s_pred[rr * 6 + c] = acc;
    }
    __syncthreads();

    // ---- scatter: out[row, idx_j] = x[row, idx_j] + pred_j, last j wins ----
    if (t < 32) {
        int g = gbase + t;
        if (g < B) {
            int row = s_row[t];
            float* o = out + (size_t)row * XDIM;
            #pragma unroll
            for (int j = 0; j < 6; j++) {
                o[s_idx[t * 8 + j]] = s_att[t * 8 + j] + s_pred[t * 6 + j];
            }
        }
    }
}

// ---------------- launch ---------------------------------------------------------
extern "C" void kernel_launch(void* const* d_in, const int* in_sizes, int n_in,
                              void* d_out, int out_size) {
    const float* x   = (const float*)d_in[0];
    const float* W1  = (const float*)d_in[1];
    const float* b1  = (const float*)d_in[2];
    const float* W2  = (const float*)d_in[3];
    const float* b2  = (const float*)d_in[4];
    const float* W3  = (const float*)d_in[5];
    const float* b3  = (const float*)d_in[6];
    const float* W4  = (const float*)d_in[7];
    const float* b4  = (const float*)d_in[8];
    const int*   act = (const int*)d_in[9];
    float* out = (float*)d_out;

    int B = in_sizes[0] / XDIM;

    cudaFuncSetAttribute(k4_mlp, cudaFuncAttributeMaxDynamicSharedMemorySize, SMEM_BYTES);

    k0_zero<<<1, 32>>>();
    k1_prep<<<(B + 7) / 8, 256>>>(x, act, out, B);
    k2_bases<<<1, 1>>>();
    k3_assign<<<(B + 255) / 256, 256>>>(act, B);
    k4_mlp<<<(B + 31) / 32, 256, SMEM_BYTES>>>(W1, b1, W2, b2, W3, b3, W4, b4,
                                               act, out, B);
}

// round 2
// speedup vs baseline: 2.6204x; 2.6204x over previous
#include <cuda_runtime.h>
#include <cuda_bf16.h>
#include <cstdint>

// Problem constants (fixed shapes)
#define XDIM 362
#define GRID_STRIDE 19
#define MAXB 65536
#define PERM_CAP (MAXB + 96)

// ---------------- device scratch ----------------
__device__ float g_att[MAXB * 8];
__device__ int   g_idx[MAXB * 8];
__device__ int   g_perm[PERM_CAP];   // rows bucketed by action, padded per-bucket to x32 with -1
__device__ int   g_hist[3];
__device__ int   g_slot[3];
__device__ int   g_bases[3];         // padded bucket bases
__device__ int   g_tp;               // total padded rows

// ---------------- cp.async helpers ----------------
__device__ __forceinline__ void cp_async16(void* smem, const void* gmem) {
    unsigned s = (unsigned)__cvta_generic_to_shared(smem);
    asm volatile("cp.async.cg.shared.global [%0], [%1], 16;\n" :: "r"(s), "l"(gmem));
}
__device__ __forceinline__ void cp_commit() {
    asm volatile("cp.async.commit_group;\n");
}
__device__ __forceinline__ void cp_wait_all() {
    asm volatile("cp.async.wait_group 0;\n");
}

// ---------------- K0: zero counters ----------------
__global__ void k0_zero() {
    if (threadIdx.x < 3) {
        g_hist[threadIdx.x] = 0;
        g_slot[threadIdx.x] = 0;
    }
}

__device__ __forceinline__ int clampi(int v) {
    v = v < 1 ? 1 : v;
    return v > (XDIM - 1) ? (XDIM - 1) : v;
}

// ---------------- K1: copy x->out, argmax, gather, histogram ----------------
__global__ void k1_prep(const float* __restrict__ x, const int* __restrict__ act,
                        float* __restrict__ out, int B) {
    __shared__ int s_hist[3];
    if (threadIdx.x < 3) s_hist[threadIdx.x] = 0;
    __syncthreads();

    int warp = (blockIdx.x * blockDim.x + threadIdx.x) >> 5;
    int lane = threadIdx.x & 31;

    if (warp < B) {
        const float* xr = x + (size_t)warp * XDIM;
        float* outr = out + (size_t)warp * XDIM;

        float best = -3.402823466e+38f;
        int bidx = 0;
        for (int i = lane; i < XDIM; i += 32) {
            float v = xr[i];
            outr[i] = v;
            if (v > best) { best = v; bidx = i; }
        }
        #pragma unroll
        for (int off = 16; off; off >>= 1) {
            float ov = __shfl_xor_sync(0xffffffffu, best, off);
            int   oi = __shfl_xor_sync(0xffffffffu, bidx, off);
            if (ov > best || (ov == best && oi < bidx)) { best = ov; bidx = oi; }
        }
        if (lane == 0) {
            int ptr = bidx;
            int id[6];
            id[0] = 0;
            id[1] = ptr;                        // unclamped, as in source
            id[2] = clampi(ptr - GRID_STRIDE);
            id[3] = clampi(ptr + GRID_STRIDE);
            id[4] = clampi(ptr - 1);
            id[5] = clampi(ptr + 1);
            #pragma unroll
            for (int j = 0; j < 6; j++) {
                g_idx[warp * 8 + j] = id[j];
                g_att[warp * 8 + j] = xr[id[j]];
            }
            atomicAdd(&s_hist[act[warp]], 1);
        }
    }
    __syncthreads();
    if (threadIdx.x < 3) atomicAdd(&g_hist[threadIdx.x], s_hist[threadIdx.x]);
}

// ---------------- K2: padded bases + fill pad slots with -1 ----------------
__global__ void k2_bases() {
    int c0 = g_hist[0], c1 = g_hist[1], c2 = g_hist[2];
    int p0 = 0;
    int p1 = ((c0 + 31) / 32) * 32;
    int p2 = p1 + ((c1 + 31) / 32) * 32;
    int tp = p2 + ((c2 + 31) / 32) * 32;
    g_bases[0] = p0; g_bases[1] = p1; g_bases[2] = p2; g_tp = tp;
    for (int s = p0 + c0; s < p1; s++) g_perm[s] = -1;
    for (int s = p1 + c1; s < p2; s++) g_perm[s] = -1;
    for (int s = p2 + c2; s < tp; s++) g_perm[s] = -1;
}

// ---------------- K3: bucket assignment (warp-aggregated atomics) ----------------
__global__ void k3_assign(const int* __restrict__ act, int B) {
    int i = blockIdx.x * blockDim.x + threadIdx.x;
    int lane = threadIdx.x & 31;
    int a = (i < B) ? act[i] : -1;
    #pragma unroll
    for (int aa = 0; aa < 3; aa++) {
        unsigned m = __ballot_sync(0xffffffffu, a == aa);
        if (a == aa) {
            int leader = __ffs(m) - 1;
            int base = 0;
            if (lane == leader) base = atomicAdd(&g_slot[aa], __popc(m));
            base = __shfl_sync(m, base, leader);
            int off = __popc(m & ((1u << lane) - 1u));
            g_perm[g_bases[aa] + base + off] = i;
        }
    }
}

// ---------------- K4: fused MLP, action-uniform blocks, smem-staged weights ------
#define H1_STRIDE 101
#define H2_STRIDE 405
#define H3_STRIDE 101
#define WBUF_F 3200              // floats per weight buffer (max: W2 tile 8x400)
// floats: wbuf(2*3200) h1(32*101) h2(32*405) h3(32*101) att(256) pred(192)
#define SMEM_F (2*WBUF_F + 32*H1_STRIDE + 32*H2_STRIDE + 32*H3_STRIDE + 256 + 192)
#define SMEM_I (32*8 + 32)
#define SMEM_BYTES (SMEM_F*4 + SMEM_I*4)

__global__ void __launch_bounds__(256, 2)
k4_mlp(const float* __restrict__ W1, const float* __restrict__ b1,
       const float* __restrict__ W2, const float* __restrict__ b2,
       const float* __restrict__ W3, const float* __restrict__ b3,
       const float* __restrict__ W4, const float* __restrict__ b4,
       float* __restrict__ out) {
    extern __shared__ float sm[];
    float* s_wbuf = sm;                         // 2*WBUF_F, 16B aligned
    float* s_h1   = s_wbuf + 2 * WBUF_F;
    float* s_h2   = s_h1 + 32 * H1_STRIDE;
    float* s_h3   = s_h2 + 32 * H2_STRIDE;
    float* s_att  = s_h3 + 32 * H3_STRIDE;      // 32*8
    float* s_pred = s_att + 32 * 8;             // 32*6
    int*   s_idx  = (int*)(s_pred + 32 * 6);    // 32*8
    int*   s_row  = s_idx + 32 * 8;             // 32

    const int t = threadIdx.x;
    const int gstart = blockIdx.x * 32;
    if (gstart >= g_tp) return;

    // block-uniform action
    const int a = (gstart >= g_bases[2]) ? 2 : (gstart >= g_bases[1]) ? 1 : 0;

    if (t < 32) {
        int row = g_perm[gstart + t];
        s_row[t] = row;
        if (row >= 0) {
            #pragma unroll
            for (int j = 0; j < 8; j++) {
                s_att[t * 8 + j] = g_att[row * 8 + j];
                s_idx[t * 8 + j] = g_idx[row * 8 + j];
            }
        } else {
            #pragma unroll
            for (int j = 0; j < 8; j++) { s_att[t * 8 + j] = 0.f; s_idx[t * 8 + j] = 0; }
        }
    }
    __syncthreads();

    const int r  = t & 31;   // row of the tile owned by this thread
    const int wg = t >> 5;   // 0..7 warp id -> column-group phase

    // ---- layer 1: att[6] -> h1[100], relu (direct global; tiny) ----
    {
        const float* w  = W1 + a * 600;
        const float* bb = b1 + a * 100;
        for (int ng = wg; ng < 25; ng += 8) {
            int n = ng * 4;
            float4 acc = *(const float4*)(bb + n);
            #pragma unroll
            for (int k = 0; k < 6; k++) {
                float  av = s_att[r * 8 + k];
                float4 wv = *(const float4*)(w + k * 100 + n);
                acc.x += av * wv.x; acc.y += av * wv.y;
                acc.z += av * wv.z; acc.w += av * wv.w;
            }
            float* dst = s_h1 + r * H1_STRIDE + n;
            dst[0] = fmaxf(acc.x, 0.f); dst[1] = fmaxf(acc.y, 0.f);
            dst[2] = fmaxf(acc.z, 0.f); dst[3] = fmaxf(acc.w, 0.f);
        }
    }
    __syncthreads();

    // ---- layer 2: h1[100] -> h2[400], relu. K tiled (KT=8), cp.async dbl-buffer.
    // warp wg owns col groups ng = wg + 8j (j<13, ng<100); acc persistent in regs.
    {
        const float* w  = W2 + a * 40000;   // [100,400]
        const float* bb = b2 + a * 400;
        float4 acc[13];
        #pragma unroll
        for (int j = 0; j < 13; j++) {
            int ng = wg + 8 * j;
            if (ng < 100) acc[j] = *(const float4*)(bb + ng * 4);
        }
        const int NT = 13;  // tiles: 12 of 8 rows + 1 of 4 rows
        // prologue: stage tile 0
        {
            const float4* src = (const float4*)w;
            float4* dst = (float4*)s_wbuf;
            for (int i = t; i < 800; i += 256) cp_async16(dst + i, src + i);
            cp_commit();
        }
        for (int kt = 0; kt < NT; kt++) {
            cp_wait_all();
            __syncthreads();
            if (kt + 1 < NT) {
                int nf4 = (kt + 1 < 12) ? 800 : 400;
                const float4* src = (const float4*)(w + (kt + 1) * 3200);
                float4* dst = (float4*)(s_wbuf + ((kt + 1) & 1) * WBUF_F);
                for (int i = t; i < nf4; i += 256) cp_async16(dst + i, src + i);
                cp_commit();
            }
            const float* wt = s_wbuf + (kt & 1) * WBUF_F;
            int klim = (kt < 12) ? 8 : 4;
            const float* hr = s_h1 + r * H1_STRIDE + kt * 8;
            for (int kk = 0; kk < klim; kk++) {
                float av = hr[kk];
                const float* wrow = wt + kk * 400;
                #pragma unroll
                for (int j = 0; j < 13; j++) {
                    int ng = wg + 8 * j;
                    if (ng < 100) {
                        float4 wv = *(const float4*)(wrow + ng * 4);
                        acc[j].x += av * wv.x; acc[j].y += av * wv.y;
                        acc[j].z += av * wv.z; acc[j].w += av * wv.w;
                    }
                }
            }
        }
        __syncthreads();   // all reads of wbuf done before layer-3 staging
        #pragma unroll
        for (int j = 0; j < 13; j++) {
            int ng = wg + 8 * j;
            if (ng < 100) {
                float* dst = s_h2 + r * H2_STRIDE + ng * 4;
                dst[0] = fmaxf(acc[j].x, 0.f); dst[1] = fmaxf(acc[j].y, 0.f);
                dst[2] = fmaxf(acc[j].z, 0.f); dst[3] = fmaxf(acc[j].w, 0.f);
            }
        }
        __syncthreads();
    }

    // ---- layer 3: h2[400] -> h3[100], relu. K tiled (KT=16), cp.async dbl-buffer.
    // warp wg owns col groups ng = wg + 8j (j<4, ng<25).
    {
        const float* w  = W3 + a * 40000;   // [400,100]
        const float* bb = b3 + a * 100;
        float4 acc[4];
        #pragma unroll
        for (int j = 0; j < 4; j++) {
            int ng = wg + 8 * j;
            if (ng < 25) acc[j] = *(const float4*)(bb + ng * 4);
        }
        const int NT = 25;  // 25 tiles of 16 rows (16*25=400)
        {
            const float4* src = (const float4*)w;
            float4* dst = (float4*)s_wbuf;
            for (int i = t; i < 400; i += 256) cp_async16(dst + i, src + i);
            cp_commit();
        }
        for (int kt = 0; kt < NT; kt++) {
            cp_wait_all();
            __syncthreads();
            if (kt + 1 < NT) {
                const float4* src = (const float4*)(w + (kt + 1) * 1600);
                float4* dst = (float4*)(s_wbuf + ((kt + 1) & 1) * WBUF_F);
                for (int i = t; i < 400; i += 256) cp_async16(dst + i, src + i);
                cp_commit();
            }
            const float* wt = s_wbuf + (kt & 1) * WBUF_F;
            const float* hr = s_h2 + r * H2_STRIDE + kt * 16;
            #pragma unroll 4
            for (int kk = 0; kk < 16; kk++) {
                float av = hr[kk];
                const float* wrow = wt + kk * 100;
                #pragma unroll
                for (int j = 0; j < 4; j++) {
                    int ng = wg + 8 * j;
                    if (ng < 25) {
                        float4 wv = *(const float4*)(wrow + ng * 4);
                        acc[j].x += av * wv.x; acc[j].y += av * wv.y;
                        acc[j].z += av * wv.z; acc[j].w += av * wv.w;
                    }
                }
            }
        }
        __syncthreads();
        #pragma unroll
        for (int j = 0; j < 4; j++) {
            int ng = wg + 8 * j;
            if (ng < 25) {
                float* dst = s_h3 + r * H3_STRIDE + ng * 4;
                dst[0] = fmaxf(acc[j].x, 0.f); dst[1] = fmaxf(acc[j].y, 0.f);
                dst[2] = fmaxf(acc[j].z, 0.f); dst[3] = fmaxf(acc[j].w, 0.f);
            }
        }
        __syncthreads();
    }

    // ---- layer 4: h3[100] -> pred[6] (no relu) ----
    if (t < 192) {
        int rr = t & 31;
        int c  = t >> 5;                  // 0..5
        const float* w   = W4 + a * 600;  // [100,6]
        const float* hr3 = s_h3 + rr * H3_STRIDE;
        float acc = b4[a * 6 + c];
        #pragma unroll 4
        for (int k = 0; k < 100; k++) acc += hr3[k] * w[k * 6 + c];
        s_pred[rr * 6 + c] = acc;
    }
    __syncthreads();

    // ---- scatter: out[row, idx_j] = x[row, idx_j] + pred_j, last j wins ----
    if (t < 32) {
        int row = s_row[t];
        if (row >= 0) {
            float* o = out + (size_t)row * XDIM;
            #pragma unroll
            for (int j = 0; j < 6; j++) {
                o[s_idx[t * 8 + j]] = s_att[t * 8 + j] + s_pred[t * 6 + j];
            }
        }
    }
}

// ---------------- launch ----------------
extern "C" void kernel_launch(void* const* d_in, const int* in_sizes, int n_in,
                              void* d_out, int out_size) {
    const float* x   = (const float*)d_in[0];
    const float* W1  = (const float*)d_in[1];
    const float* b1  = (const float*)d_in[2];
    const float* W2  = (const float*)d_in[3];
    const float* b2  = (const float*)d_in[4];
    const float* W3  = (const float*)d_in[5];
    const float* b3  = (const float*)d_in[6];
    const float* W4  = (const float*)d_in[7];
    const float* b4  = (const float*)d_in[8];
    const int*   act = (const int*)d_in[9];
    float* out = (float*)d_out;

    int B = in_sizes[0] / XDIM;

    static bool attr_set = false;
    if (!attr_set) {
        cudaFuncSetAttribute(k4_mlp, cudaFuncAttributeMaxDynamicSharedMemorySize, SMEM_BYTES);
        attr_set = true;
    }

    int k4_blocks = (B + 96) / 32;   // upper bound incl. per-bucket padding

    k0_zero<<<1, 32>>>();
    k1_prep<<<(B + 7) / 8, 256>>>(x, act, out, B);
    k2_bases<<<1, 1>>>();
    k3_assign<<<(B + 255) / 256, 256>>>(act, B);
    k4_mlp<<<k4_blocks, 256, SMEM_BYTES>>>(W1, b1, W2, b2, W3, b3, W4, b4, out);
}

// round 3
// speedup vs baseline: 2.9306x; 1.1184x over previous
#include <cuda_runtime.h>
#include <cuda_bf16.h>
#include <cstdint>

// Problem constants (fixed shapes)
#define XDIM 362
#define GRID_STRIDE 19
#define MAXB 65536
#define PERM_CAP (MAXB + 96)

// ---------------- device scratch ----------------
__device__ float g_att[MAXB * 8];
__device__ int   g_idx[MAXB * 8];
__device__ int   g_perm[PERM_CAP];   // rows bucketed by action, padded per-bucket to x32 with -1
__device__ int   g_hist[3];
__device__ int   g_slot[3];
__device__ int   g_bases[3];         // padded bucket bases
__device__ int   g_tp;               // total padded rows

// ---------------- cp.async helpers ----------------
__device__ __forceinline__ void cp_async16(void* smem, const void* gmem) {
    unsigned s = (unsigned)__cvta_generic_to_shared(smem);
    asm volatile("cp.async.cg.shared.global [%0], [%1], 16;\n" :: "r"(s), "l"(gmem));
}
__device__ __forceinline__ void cp_commit() {
    asm volatile("cp.async.commit_group;\n");
}
__device__ __forceinline__ void cp_wait_all() {
    asm volatile("cp.async.wait_group 0;\n");
}

// ---------------- packed f32x2 FMA (Blackwell FFMA2; ptxas never auto-fuses) ----
__device__ __forceinline__ unsigned long long ffma2(unsigned long long a,
                                                    unsigned long long b,
                                                    unsigned long long c) {
    unsigned long long d;
    asm("fma.rn.f32x2 %0, %1, %2, %3;" : "=l"(d) : "l"(a), "l"(b), "l"(c));
    return d;
}
__device__ __forceinline__ unsigned long long pack2(float v) {
    unsigned long long d;
    asm("mov.b64 %0, {%1, %1};" : "=l"(d) : "f"(v));
    return d;
}
union U64F2 { unsigned long long u; float2 f; };

// ---------------- K0: zero counters ----------------
__global__ void k0_zero() {
    if (threadIdx.x < 3) {
        g_hist[threadIdx.x] = 0;
        g_slot[threadIdx.x] = 0;
    }
}

__device__ __forceinline__ int clampi(int v) {
    v = v < 1 ? 1 : v;
    return v > (XDIM - 1) ? (XDIM - 1) : v;
}

// ---------------- K1: copy x->out, argmax, gather, histogram ----------------
__global__ void k1_prep(const float* __restrict__ x, const int* __restrict__ act,
                        float* __restrict__ out, int B) {
    __shared__ int s_hist[3];
    if (threadIdx.x < 3) s_hist[threadIdx.x] = 0;
    __syncthreads();

    int warp = (blockIdx.x * blockDim.x + threadIdx.x) >> 5;
    int lane = threadIdx.x & 31;

    if (warp < B) {
        const float* xr = x + (size_t)warp * XDIM;
        float* outr = out + (size_t)warp * XDIM;

        float best = -3.402823466e+38f;
        int bidx = 0;
        for (int i = lane; i < XDIM; i += 32) {
            float v = xr[i];
            outr[i] = v;
            if (v > best) { best = v; bidx = i; }
        }
        #pragma unroll
        for (int off = 16; off; off >>= 1) {
            float ov = __shfl_xor_sync(0xffffffffu, best, off);
            int   oi = __shfl_xor_sync(0xffffffffu, bidx, off);
            if (ov > best || (ov == best && oi < bidx)) { best = ov; bidx = oi; }
        }
        if (lane == 0) {
            int ptr = bidx;
            int id[6];
            id[0] = 0;
            id[1] = ptr;                        // unclamped, as in source
            id[2] = clampi(ptr - GRID_STRIDE);
            id[3] = clampi(ptr + GRID_STRIDE);
            id[4] = clampi(ptr - 1);
            id[5] = clampi(ptr + 1);
            #pragma unroll
            for (int j = 0; j < 6; j++) {
                g_idx[warp * 8 + j] = id[j];
                g_att[warp * 8 + j] = xr[id[j]];
            }
            atomicAdd(&s_hist[act[warp]], 1);
        }
    }
    __syncthreads();
    if (threadIdx.x < 3) atomicAdd(&g_hist[threadIdx.x], s_hist[threadIdx.x]);
}

// ---------------- K2: padded bases + fill pad slots with -1 ----------------
__global__ void k2_bases() {
    int c0 = g_hist[0], c1 = g_hist[1], c2 = g_hist[2];
    int p0 = 0;
    int p1 = ((c0 + 31) / 32) * 32;
    int p2 = p1 + ((c1 + 31) / 32) * 32;
    int tp = p2 + ((c2 + 31) / 32) * 32;
    g_bases[0] = p0; g_bases[1] = p1; g_bases[2] = p2; g_tp = tp;
    for (int s = p0 + c0; s < p1; s++) g_perm[s] = -1;
    for (int s = p1 + c1; s < p2; s++) g_perm[s] = -1;
    for (int s = p2 + c2; s < tp; s++) g_perm[s] = -1;
}

// ---------------- K3: bucket assignment (warp-aggregated atomics) ----------------
__global__ void k3_assign(const int* __restrict__ act, int B) {
    int i = blockIdx.x * blockDim.x + threadIdx.x;
    int lane = threadIdx.x & 31;
    int a = (i < B) ? act[i] : -1;
    #pragma unroll
    for (int aa = 0; aa < 3; aa++) {
        unsigned m = __ballot_sync(0xffffffffu, a == aa);
        if (a == aa) {
            int leader = __ffs(m) - 1;
            int base = 0;
            if (lane == leader) base = atomicAdd(&g_slot[aa], __popc(m));
            base = __shfl_sync(m, base, leader);
            int off = __popc(m & ((1u << lane) - 1u));
            g_perm[g_bases[aa] + base + off] = i;
        }
    }
}

// ---------------- K4: fused MLP, action-uniform blocks, smem weights, FFMA2 ------
#define H1_STRIDE 101
#define H2_STRIDE 405
#define H3_STRIDE 101
#define WBUF_F 3200              // floats per weight buffer (max: W2 tile 8x400)
#define SMEM_F (2*WBUF_F + 32*H1_STRIDE + 32*H2_STRIDE + 32*H3_STRIDE + 256 + 192)
#define SMEM_I (32*8 + 32)
#define SMEM_BYTES (SMEM_F*4 + SMEM_I*4)

__global__ void __launch_bounds__(256, 2)
k4_mlp(const float* __restrict__ W1, const float* __restrict__ b1,
       const float* __restrict__ W2, const float* __restrict__ b2,
       const float* __restrict__ W3, const float* __restrict__ b3,
       const float* __restrict__ W4, const float* __restrict__ b4,
       float* __restrict__ out) {
    extern __shared__ float sm[];
    float* s_wbuf = sm;                         // 2*WBUF_F, 16B aligned
    float* s_h1   = s_wbuf + 2 * WBUF_F;
    float* s_h2   = s_h1 + 32 * H1_STRIDE;
    float* s_h3   = s_h2 + 32 * H2_STRIDE;
    float* s_att  = s_h3 + 32 * H3_STRIDE;      // 32*8
    float* s_pred = s_att + 32 * 8;             // 32*6
    int*   s_idx  = (int*)(s_pred + 32 * 6);    // 32*8
    int*   s_row  = s_idx + 32 * 8;             // 32

    const int t = threadIdx.x;
    const int gstart = blockIdx.x * 32;
    if (gstart >= g_tp) return;

    // block-uniform action
    const int a = (gstart >= g_bases[2]) ? 2 : (gstart >= g_bases[1]) ? 1 : 0;

    if (t < 32) {
        int row = g_perm[gstart + t];
        s_row[t] = row;
        if (row >= 0) {
            #pragma unroll
            for (int j = 0; j < 8; j++) {
                s_att[t * 8 + j] = g_att[row * 8 + j];
                s_idx[t * 8 + j] = g_idx[row * 8 + j];
            }
        } else {
            #pragma unroll
            for (int j = 0; j < 8; j++) { s_att[t * 8 + j] = 0.f; s_idx[t * 8 + j] = 0; }
        }
    }
    __syncthreads();

    const int r  = t & 31;   // row of the tile owned by this thread
    const int wg = t >> 5;   // 0..7 warp id -> column-group phase

    // ---- layer 1: att[6] -> h1[100], relu (direct global; tiny) ----
    {
        const float* w  = W1 + a * 600;
        const float* bb = b1 + a * 100;
        for (int ng = wg; ng < 25; ng += 8) {
            int n = ng * 4;
            float4 acc = *(const float4*)(bb + n);
            #pragma unroll
            for (int k = 0; k < 6; k++) {
                float  av = s_att[r * 8 + k];
                float4 wv = *(const float4*)(w + k * 100 + n);
                acc.x += av * wv.x; acc.y += av * wv.y;
                acc.z += av * wv.z; acc.w += av * wv.w;
            }
            float* dst = s_h1 + r * H1_STRIDE + n;
            dst[0] = fmaxf(acc.x, 0.f); dst[1] = fmaxf(acc.y, 0.f);
            dst[2] = fmaxf(acc.z, 0.f); dst[3] = fmaxf(acc.w, 0.f);
        }
    }
    __syncthreads();

    // ---- layer 2: h1[100] -> h2[400], relu. K tiled (KT=8), cp.async dbl-buffer,
    //      packed f32x2 FMAs (26 FFMA2/thread/k instead of 52 FFMA).
    {
        const float* w  = W2 + a * 40000;   // [100,400]
        const float* bb = b2 + a * 400;
        ulonglong2 acc[13];
        #pragma unroll
        for (int j = 0; j < 13; j++) {
            int ng = wg + 8 * j;
            if (ng < 100) acc[j] = *(const ulonglong2*)(bb + ng * 4);
        }
        const int NT = 13;  // tiles: 12 of 8 rows + 1 of 4 rows
        {
            const float4* src = (const float4*)w;
            float4* dst = (float4*)s_wbuf;
            for (int i = t; i < 800; i += 256) cp_async16(dst + i, src + i);
            cp_commit();
        }
        for (int kt = 0; kt < NT; kt++) {
            cp_wait_all();
            __syncthreads();
            if (kt + 1 < NT) {
                int nf4 = (kt + 1 < 12) ? 800 : 400;
                const float4* src = (const float4*)(w + (kt + 1) * 3200);
                float4* dst = (float4*)(s_wbuf + ((kt + 1) & 1) * WBUF_F);
                for (int i = t; i < nf4; i += 256) cp_async16(dst + i, src + i);
                cp_commit();
            }
            const float* wt = s_wbuf + (kt & 1) * WBUF_F;
            int klim = (kt < 12) ? 8 : 4;
            const float* hr = s_h1 + r * H1_STRIDE + kt * 8;
            for (int kk = 0; kk < klim; kk++) {
                unsigned long long av2 = pack2(hr[kk]);
                const float* wrow = wt + kk * 400;
                #pragma unroll
                for (int j = 0; j < 13; j++) {
                    int ng = wg + 8 * j;
                    if (ng < 100) {
                        ulonglong2 wv = *(const ulonglong2*)(wrow + ng * 4);
                        acc[j].x = ffma2(av2, wv.x, acc[j].x);
                        acc[j].y = ffma2(av2, wv.y, acc[j].y);
                    }
                }
            }
        }
        __syncthreads();   // all reads of wbuf done before layer-3 staging
        #pragma unroll
        for (int j = 0; j < 13; j++) {
            int ng = wg + 8 * j;
            if (ng < 100) {
                U64F2 lo, hi; lo.u = acc[j].x; hi.u = acc[j].y;
                float* dst = s_h2 + r * H2_STRIDE + ng * 4;
                dst[0] = fmaxf(lo.f.x, 0.f); dst[1] = fmaxf(lo.f.y, 0.f);
                dst[2] = fmaxf(hi.f.x, 0.f); dst[3] = fmaxf(hi.f.y, 0.f);
            }
        }
        __syncthreads();
    }

    // ---- layer 3: h2[400] -> h3[100], relu. K tiled (KT=16), cp.async dbl-buffer,
    //      packed f32x2 FMAs.
    {
        const float* w  = W3 + a * 40000;   // [400,100]
        const float* bb = b3 + a * 100;
        ulonglong2 acc[4];
        #pragma unroll
        for (int j = 0; j < 4; j++) {
            int ng = wg + 8 * j;
            if (ng < 25) acc[j] = *(const ulonglong2*)(bb + ng * 4);
        }
        const int NT = 25;  // 25 tiles of 16 rows
        {
            const float4* src = (const float4*)w;
            float4* dst = (float4*)s_wbuf;
            for (int i = t; i < 400; i += 256) cp_async16(dst + i, src + i);
            cp_commit();
        }
        for (int kt = 0; kt < NT; kt++) {
            cp_wait_all();
            __syncthreads();
            if (kt + 1 < NT) {
                const float4* src = (const float4*)(w + (kt + 1) * 1600);
                float4* dst = (float4*)(s_wbuf + ((kt + 1) & 1) * WBUF_F);
                for (int i = t; i < 400; i += 256) cp_async16(dst + i, src + i);
                cp_commit();
            }
            const float* wt = s_wbuf + (kt & 1) * WBUF_F;
            const float* hr = s_h2 + r * H2_STRIDE + kt * 16;
            #pragma unroll 4
            for (int kk = 0; kk < 16; kk++) {
                unsigned long long av2 = pack2(hr[kk]);
                const float* wrow = wt + kk * 100;
                #pragma unroll
                for (int j = 0; j < 4; j++) {
                    int ng = wg + 8 * j;
                    if (ng < 25) {
                        ulonglong2 wv = *(const ulonglong2*)(wrow + ng * 4);
                        acc[j].x = ffma2(av2, wv.x, acc[j].x);
                        acc[j].y = ffma2(av2, wv.y, acc[j].y);
                    }
                }
            }
        }
        __syncthreads();
        #pragma unroll
        for (int j = 0; j < 4; j++) {
            int ng = wg + 8 * j;
            if (ng < 25) {
                U64F2 lo, hi; lo.u = acc[j].x; hi.u = acc[j].y;
                float* dst = s_h3 + r * H3_STRIDE + ng * 4;
                dst[0] = fmaxf(lo.f.x, 0.f); dst[1] = fmaxf(lo.f.y, 0.f);
                dst[2] = fmaxf(hi.f.x, 0.f); dst[3] = fmaxf(hi.f.y, 0.f);
            }
        }
        __syncthreads();
    }

    // ---- layer 4: h3[100] -> pred[6] (no relu) ----
    if (t < 192) {
        int rr = t & 31;
        int c  = t >> 5;                  // 0..5
        const float* w   = W4 + a * 600;  // [100,6]
        const float* hr3 = s_h3 + rr * H3_STRIDE;
        float acc = b4[a * 6 + c];
        #pragma unroll 4
        for (int k = 0; k < 100; k++) acc += hr3[k] * w[k * 6 + c];
        s_pred[rr * 6 + c] = acc;
    }
    __syncthreads();

    // ---- scatter: out[row, idx_j] = x[row, idx_j] + pred_j, last j wins ----
    if (t < 32) {
        int row = s_row[t];
        if (row >= 0) {
            float* o = out + (size_t)row * XDIM;
            #pragma unroll
            for (int j = 0; j < 6; j++) {
                o[s_idx[t * 8 + j]] = s_att[t * 8 + j] + s_pred[t * 6 + j];
            }
        }
    }
}

// ---------------- launch ----------------
extern "C" void kernel_launch(void* const* d_in, const int* in_sizes, int n_in,
                              void* d_out, int out_size) {
    const float* x   = (const float*)d_in[0];
    const float* W1  = (const float*)d_in[1];
    const float* b1  = (const float*)d_in[2];
    const float* W2  = (const float*)d_in[3];
    const float* b2  = (const float*)d_in[4];
    const float* W3  = (const float*)d_in[5];
    const float* b3  = (const float*)d_in[6];
    const float* W4  = (const float*)d_in[7];
    const float* b4  = (const float*)d_in[8];
    const int*   act = (const int*)d_in[9];
    float* out = (float*)d_out;

    int B = in_sizes[0] / XDIM;

    static bool attr_set = false;
    if (!attr_set) {
        cudaFuncSetAttribute(k4_mlp, cudaFuncAttributeMaxDynamicSharedMemorySize, SMEM_BYTES);
        attr_set = true;
    }

    int k4_blocks = (B + 96) / 32;   // upper bound incl. per-bucket padding

    k0_zero<<<1, 32>>>();
    k1_prep<<<(B + 7) / 8, 256>>>(x, act, out, B);
    k2_bases<<<1, 1>>>();
    k3_assign<<<(B + 255) / 256, 256>>>(act, B);
    k4_mlp<<<k4_blocks, 256, SMEM_BYTES>>>(W1, b1, W2, b2, W3, b3, W4, b4, out);
}

// round 5
// speedup vs baseline: 3.1070x; 1.0602x over previous
#include <cuda_runtime.h>
#include <cuda_bf16.h>
#include <cstdint>

// Problem constants (fixed shapes)
#define XDIM 362
#define GRID_STRIDE 19
#define MAXB 65536
#define RPC 128                       // rows per CTA (M tile)
#define PERM_CAP (MAXB + 3*RPC)

// ---------------- device scratch ----------------
__device__ float g_att[MAXB * 8];
__device__ int   g_idx[MAXB * 8];
__device__ int   g_perm[PERM_CAP];
__device__ int   g_hist[3];
__device__ int   g_slot[3];
__device__ int   g_bases[3];
__device__ int   g_tp;

// ---------------- small helpers ----------------
__device__ __forceinline__ int clampi(int v) {
    v = v < 1 ? 1 : v;
    return v > (XDIM - 1) ? (XDIM - 1) : v;
}
__device__ __forceinline__ uint32_t smem_u32(const void* p) {
    return (uint32_t)__cvta_generic_to_shared(p);
}

// bf16 split: v = hi + lo (hi,lo bf16) -> ~16-bit effective mantissa
__device__ __forceinline__ void bsplit(float v, __nv_bfloat16& h, __nv_bfloat16& l) {
    h = __float2bfloat16_rn(v);
    l = __float2bfloat16_rn(v - __bfloat162float(h));
}
__device__ __forceinline__ uint32_t bf16bits(__nv_bfloat16 h) {
    __nv_bfloat16_raw r = static_cast<__nv_bfloat16_raw>(h);
    return (uint32_t)r.x;
}

// ---------------- mma / ldmatrix ----------------
__device__ __forceinline__ void mma16816(float* d, const uint32_t* a, const uint32_t* b) {
    asm volatile(
        "mma.sync.aligned.m16n8k16.row.col.f32.bf16.bf16.f32 "
        "{%0,%1,%2,%3}, {%4,%5,%6,%7}, {%8,%9}, {%0,%1,%2,%3};"
        : "+f"(d[0]), "+f"(d[1]), "+f"(d[2]), "+f"(d[3])
        : "r"(a[0]), "r"(a[1]), "r"(a[2]), "r"(a[3]), "r"(b[0]), "r"(b[1]));
}
__device__ __forceinline__ void ldmx4(uint32_t* r, uint32_t addr) {
    asm volatile("ldmatrix.sync.aligned.m8n8.x4.shared.b16 {%0,%1,%2,%3}, [%4];"
                 : "=r"(r[0]), "=r"(r[1]), "=r"(r[2]), "=r"(r[3]) : "r"(addr));
}
__device__ __forceinline__ void ldmx2t(uint32_t* r, uint32_t addr) {
    asm volatile("ldmatrix.sync.aligned.m8n8.x2.trans.shared.b16 {%0,%1}, [%2];"
                 : "=r"(r[0]), "=r"(r[1]) : "r"(addr));
}

// ---------------- K0 ----------------
__global__ void k0_zero() {
    if (threadIdx.x < 3) { g_hist[threadIdx.x] = 0; g_slot[threadIdx.x] = 0; }
}

// ---------------- K1: copy x->out, argmax, gather, histogram ----------------
__global__ void k1_prep(const float* __restrict__ x, const int* __restrict__ act,
                        float* __restrict__ out, int B) {
    __shared__ int s_hist[3];
    if (threadIdx.x < 3) s_hist[threadIdx.x] = 0;
    __syncthreads();

    int warp = (blockIdx.x * blockDim.x + threadIdx.x) >> 5;
    int lane = threadIdx.x & 31;

    if (warp < B) {
        const float* xr = x + (size_t)warp * XDIM;
        float* outr = out + (size_t)warp * XDIM;
        float best = -3.402823466e+38f;
        int bidx = 0;
        for (int i = lane; i < XDIM; i += 32) {
            float v = xr[i];
            outr[i] = v;
            if (v > best) { best = v; bidx = i; }
        }
        #pragma unroll
        for (int off = 16; off; off >>= 1) {
            float ov = __shfl_xor_sync(0xffffffffu, best, off);
            int   oi = __shfl_xor_sync(0xffffffffu, bidx, off);
            if (ov > best || (ov == best && oi < bidx)) { best = ov; bidx = oi; }
        }
        if (lane == 0) {
            int ptr = bidx;
            int id[6];
            id[0] = 0;
            id[1] = ptr;                        // unclamped, as in source
            id[2] = clampi(ptr - GRID_STRIDE);
            id[3] = clampi(ptr + GRID_STRIDE);
            id[4] = clampi(ptr - 1);
            id[5] = clampi(ptr + 1);
            #pragma unroll
            for (int j = 0; j < 6; j++) {
                g_idx[warp * 8 + j] = id[j];
                g_att[warp * 8 + j] = xr[id[j]];
            }
            atomicAdd(&s_hist[act[warp]], 1);
        }
    }
    __syncthreads();
    if (threadIdx.x < 3) atomicAdd(&g_hist[threadIdx.x], s_hist[threadIdx.x]);
}

// ---------------- K2: bases padded to 128, pad slots -1 ----------------
__global__ void k2_bases() {
    int c0 = g_hist[0], c1 = g_hist[1], c2 = g_hist[2];
    int p1 = ((c0 + RPC - 1) / RPC) * RPC;
    int p2 = p1 + ((c1 + RPC - 1) / RPC) * RPC;
    int tp = p2 + ((c2 + RPC - 1) / RPC) * RPC;
    g_bases[0] = 0; g_bases[1] = p1; g_bases[2] = p2; g_tp = tp;
    for (int s = c0; s < p1; s++) g_perm[s] = -1;
    for (int s = p1 + c1; s < p2; s++) g_perm[s] = -1;
    for (int s = p2 + c2; s < tp; s++) g_perm[s] = -1;
}

// ---------------- K3: bucket assignment ----------------
__global__ void k3_assign(const int* __restrict__ act, int B) {
    int i = blockIdx.x * blockDim.x + threadIdx.x;
    int lane = threadIdx.x & 31;
    int a = (i < B) ? act[i] : -1;
    #pragma unroll
    for (int aa = 0; aa < 3; aa++) {
        unsigned m = __ballot_sync(0xffffffffu, a == aa);
        if (a == aa) {
            int leader = __ffs(m) - 1;
            int base = 0;
            if (lane == leader) base = atomicAdd(&g_slot[aa], __popc(m));
            base = __shfl_sync(m, base, leader);
            int off = __popc(m & ((1u << lane) - 1u));
            g_perm[g_bases[aa] + base + off] = i;
        }
    }
}

// ---------------- K4: fused MLP via mma.sync bf16x3 (128 rows/CTA) ----------------
// panel strides in bf16 elements
#define KPAD2 120      // A2 (h1) row stride: 128 rows x 120 (100 real + pad), 240B rows
#define NPAD2 72       // B2 chunk [k=112][n=64 used], 144B rows
#define NPAD3 120      // B3 chunk [k=64][n=112 used], 240B rows
#define H3PAD 104

// smem byte offsets (16B aligned)
#define OFF_A2H 0
#define OFF_A2L 30720
#define OFF_B2H 61440
#define OFF_B2L 77568
#define OFF_B3H 93696
#define OFF_B3L 109056
#define OFF_H3  124416          // 128*104*4 = 53248
#define OFF_B2S 177664          // 400 f
#define OFF_B3S 179264          // 100 f (pad 448B)
#define OFF_W1S 179712          // 700 f
#define OFF_W4S 182512          // 608 f
#define OFF_ATT 184944          // 128*8 f
#define OFF_PRED 189040         // 128*6 f
#define OFF_IDX 192112          // 128*8 i
#define OFF_ROW 196208          // 128 i
#define SMEM_TOTAL 196736

__global__ void __launch_bounds__(256, 1)
k4_mlp(const float* __restrict__ W1, const float* __restrict__ b1,
       const float* __restrict__ W2, const float* __restrict__ b2,
       const float* __restrict__ W3, const float* __restrict__ b3,
       const float* __restrict__ W4, const float* __restrict__ b4,
       float* __restrict__ out) {
    extern __shared__ char smem[];
    const uint32_t sb = smem_u32(smem);

    __nv_bfloat16* a2h = (__nv_bfloat16*)(smem + OFF_A2H);
    __nv_bfloat16* a2l = (__nv_bfloat16*)(smem + OFF_A2L);
    __nv_bfloat16* b2h = (__nv_bfloat16*)(smem + OFF_B2H);
    __nv_bfloat16* b2l = (__nv_bfloat16*)(smem + OFF_B2L);
    __nv_bfloat16* b3h = (__nv_bfloat16*)(smem + OFF_B3H);
    __nv_bfloat16* b3l = (__nv_bfloat16*)(smem + OFF_B3L);
    float* s_h3   = (float*)(smem + OFF_H3);
    float* s_b2   = (float*)(smem + OFF_B2S);
    float* s_b3   = (float*)(smem + OFF_B3S);
    float* s_w1   = (float*)(smem + OFF_W1S);
    float* s_w4   = (float*)(smem + OFF_W4S);
    float* s_att  = (float*)(smem + OFF_ATT);
    float* s_pred = (float*)(smem + OFF_PRED);
    int*   s_idx  = (int*)(smem + OFF_IDX);
    int*   s_row  = (int*)(smem + OFF_ROW);

    const int t = threadIdx.x;
    const int lane = t & 31;
    const int wid = t >> 5;
    const int gid = lane >> 2;     // 0..7
    const int tid4 = lane & 3;     // 0..3
    const int gstart = blockIdx.x * RPC;
    if (gstart >= g_tp) return;
    const int a = (gstart >= g_bases[2]) ? 2 : (gstart >= g_bases[1]) ? 1 : 0;

    const float* w2g = W2 + a * 40000;
    const float* w3g = W3 + a * 40000;

    // ---- stage small params + row metadata, zero pads ----
    for (int i = t; i < 600; i += 256) s_w1[i] = W1[a * 600 + i];
    for (int i = t; i < 100; i += 256) s_w1[600 + i] = b1[a * 100 + i];
    for (int i = t; i < 600; i += 256) s_w4[i] = W4[a * 600 + i];
    if (t < 6) s_w4[600 + t] = b4[a * 6 + t];
    for (int i = t; i < 400; i += 256) s_b2[i] = b2[a * 400 + i];
    for (int i = t; i < 100; i += 256) s_b3[i] = b3[a * 100 + i];
    // A2 pad cols 100..119 = 0
    for (int i = t; i < 128 * 20; i += 256) {
        int r = i / 20, c = 100 + i % 20;
        a2h[r * KPAD2 + c] = __float2bfloat16(0.f);
        a2l[r * KPAD2 + c] = __float2bfloat16(0.f);
    }
    // B2 pad rows k=100..111 = 0
    for (int i = t; i < 12 * NPAD2; i += 256) {
        int k = 100 + i / NPAD2, c = i % NPAD2;
        b2h[k * NPAD2 + c] = __float2bfloat16(0.f);
        b2l[k * NPAD2 + c] = __float2bfloat16(0.f);
    }
    // B3 pad cols n=100..119 = 0
    for (int i = t; i < 64 * 20; i += 256) {
        int k = i / 20, c = 100 + i % 20;
        b3h[k * NPAD3 + c] = __float2bfloat16(0.f);
        b3l[k * NPAD3 + c] = __float2bfloat16(0.f);
    }
    if (t < RPC) {
        int row = g_perm[gstart + t];
        s_row[t] = row;
        if (row >= 0) {
            #pragma unroll
            for (int j = 0; j < 8; j++) {
                s_att[t * 8 + j] = g_att[row * 8 + j];
                s_idx[t * 8 + j] = g_idx[row * 8 + j];
            }
        } else {
            #pragma unroll
            for (int j = 0; j < 8; j++) { s_att[t * 8 + j] = 0.f; s_idx[t * 8 + j] = 0; }
        }
    }
    __syncthreads();

    // ---- layer 1 on cores: att[128,6] -> h1[128,100], split into A2 panels ----
    for (int o = t; o < RPC * 100; o += 256) {
        int r = o / 100, c = o % 100;
        float acc = s_w1[600 + c];
        #pragma unroll
        for (int k = 0; k < 6; k++) acc += s_att[r * 8 + k] * s_w1[k * 100 + c];
        float v = fmaxf(acc, 0.f);
        __nv_bfloat16 hb, lb; bsplit(v, hb, lb);
        a2h[r * KPAD2 + c] = hb;
        a2l[r * KPAD2 + c] = lb;
    }

    // ---- fused layers 2+3: 7 chunks of h2 columns (6x64 + 1x16) ----
    float acc3[14][4];
    #pragma unroll
    for (int j = 0; j < 14; j++) { acc3[j][0]=0.f; acc3[j][1]=0.f; acc3[j][2]=0.f; acc3[j][3]=0.f; }

    const int mrow = 16 * wid;   // warp's M strip

    for (int c = 0; c < 7; c++) {
        const int cbase = c * 64;
        const int width = (c < 6) ? 64 : 16;
        const int ntiles = width >> 3;

        __syncthreads();   // previous chunk's B-panel reads done
        // stage B2 chunk: [k<100][nl<width] from W2[k][cbase+nl]
        for (int i = t; i < 100 * width; i += 256) {
            int k = i / width, nl = i % width;
            float v = w2g[k * 400 + cbase + nl];
            __nv_bfloat16 hb, lb; bsplit(v, hb, lb);
            b2h[k * NPAD2 + nl] = hb;
            b2l[k * NPAD2 + nl] = lb;
        }
        // stage B3 chunk: [kl<width][n<100] from W3[cbase+kl][n]
        for (int i = t; i < width * 100; i += 256) {
            int kl = i / 100, n = i % 100;
            float v = w3g[(cbase + kl) * 100 + n];
            __nv_bfloat16 hb, lb; bsplit(v, hb, lb);
            b3h[kl * NPAD3 + n] = hb;
            b3l[kl * NPAD3 + n] = lb;
        }
        __syncthreads();

        // -- layer 2 chunk: acc2[ntiles][4] over K2=112 (7 ksteps) --
        float acc2[8][4];
        #pragma unroll
        for (int j = 0; j < 8; j++) {
            if (j < ntiles) {
                float bv0 = s_b2[cbase + 8 * j + tid4 * 2];
                float bv1 = s_b2[cbase + 8 * j + tid4 * 2 + 1];
                acc2[j][0] = bv0; acc2[j][1] = bv1; acc2[j][2] = bv0; acc2[j][3] = bv1;
            }
        }
        const uint32_t arow = (uint32_t)(mrow + (lane & 15));
        const uint32_t acolofs = (uint32_t)((lane >> 4) << 3);
        #pragma unroll
        for (int ks = 0; ks < 7; ks++) {
            uint32_t ah[4], al[4];
            uint32_t acol = (uint32_t)(ks * 16) + acolofs;
            ldmx4(ah, sb + OFF_A2H + (arow * KPAD2 + acol) * 2);
            ldmx4(al, sb + OFF_A2L + (arow * KPAD2 + acol) * 2);
            const uint32_t krow = (uint32_t)(ks * 16 + (lane & 15));
            for (int j = 0; j < ntiles; j++) {
                uint32_t bh[2], bl[2];
                uint32_t boff = (krow * NPAD2 + (uint32_t)(j * 8)) * 2;
                ldmx2t(bh, sb + OFF_B2H + boff);
                ldmx2t(bl, sb + OFF_B2L + boff);
                mma16816(acc2[j], ah, bh);
                mma16816(acc2[j], ah, bl);
                mma16816(acc2[j], al, bh);
            }
        }

        // -- relu + bf16-split in registers -> A3 frags; layer 3 accumulate --
        const int ksteps3 = ntiles >> 1;   // width/16
        for (int g = 0; g < ksteps3; g++) {
            float v0, v1;
            uint32_t a3h[4], a3l[4];
            __nv_bfloat16 h0, l0, h1, l1;
            // reg0: tile 2g (c0,c1); reg1: tile 2g (c2,c3); reg2/3: tile 2g+1
            v0 = fmaxf(acc2[2*g][0], 0.f);   v1 = fmaxf(acc2[2*g][1], 0.f);
            bsplit(v0, h0, l0); bsplit(v1, h1, l1);
            a3h[0] = bf16bits(h0) | (bf16bits(h1) << 16);
            a3l[0] = bf16bits(l0) | (bf16bits(l1) << 16);
            v0 = fmaxf(acc2[2*g][2], 0.f);   v1 = fmaxf(acc2[2*g][3], 0.f);
            bsplit(v0, h0, l0); bsplit(v1, h1, l1);
            a3h[1] = bf16bits(h0) | (bf16bits(h1) << 16);
            a3l[1] = bf16bits(l0) | (bf16bits(l1) << 16);
            v0 = fmaxf(acc2[2*g+1][0], 0.f); v1 = fmaxf(acc2[2*g+1][1], 0.f);
            bsplit(v0, h0, l0); bsplit(v1, h1, l1);
            a3h[2] = bf16bits(h0) | (bf16bits(h1) << 16);
            a3l[2] = bf16bits(l0) | (bf16bits(l1) << 16);
            v0 = fmaxf(acc2[2*g+1][2], 0.f); v1 = fmaxf(acc2[2*g+1][3], 0.f);
            bsplit(v0, h0, l0); bsplit(v1, h1, l1);
            a3h[3] = bf16bits(h0) | (bf16bits(h1) << 16);
            a3l[3] = bf16bits(l0) | (bf16bits(l1) << 16);

            const uint32_t krow3 = (uint32_t)(g * 16 + (lane & 15));
            #pragma unroll
            for (int j3 = 0; j3 < 14; j3++) {
                uint32_t bh[2], bl[2];
                uint32_t boff = (krow3 * NPAD3 + (uint32_t)(j3 * 8)) * 2;
                ldmx2t(bh, sb + OFF_B3H + boff);
                ldmx2t(bl, sb + OFF_B3L + boff);
                mma16816(acc3[j3], a3h, bh);
                mma16816(acc3[j3], a3h, bl);
                mma16816(acc3[j3], a3l, bh);
            }
        }
    }

    // ---- layer-3 epilogue: acc3 + b3, relu -> s_h3 ----
    #pragma unroll
    for (int j = 0; j < 13; j++) {
        #pragma unroll
        for (int q = 0; q < 4; q++) {
            int n = 8 * j + tid4 * 2 + (q & 1);
            int row = mrow + gid + ((q >= 2) ? 8 : 0);
            if (n < 100)
                s_h3[row * H3PAD + n] = fmaxf(acc3[j][q] + s_b3[n], 0.f);
        }
    }
    __syncthreads();

    // ---- layer 4 on cores: h3[128,100] -> pred[128,6] ----
    for (int o = t; o < RPC * 6; o += 256) {
        int r = o / 6, cc = o % 6;
        float acc = s_w4[600 + cc];
        #pragma unroll 4
        for (int k = 0; k < 100; k++) acc += s_h3[r * H3PAD + k] * s_w4[k * 6 + cc];
        s_pred[o] = acc;
    }
    __syncthreads();

    // ---- scatter ----
    if (t < RPC) {
        int row = s_row[t];
        if (row >= 0) {
            float* o = out + (size_t)row * XDIM;
            #pragma unroll
            for (int j = 0; j < 6; j++)
                o[s_idx[t * 8 + j]] = s_att[t * 8 + j] + s_pred[t * 6 + j];
        }
    }
}

// ---------------- launch ----------------
extern "C" void kernel_launch(void* const* d_in, const int* in_sizes, int n_in,
                              void* d_out, int out_size) {
    const float* x   = (const float*)d_in[0];
    const float* W1  = (const float*)d_in[1];
    const float* b1  = (const float*)d_in[2];
    const float* W2  = (const float*)d_in[3];
    const float* b2  = (const float*)d_in[4];
    const float* W3  = (const float*)d_in[5];
    const float* b3  = (const float*)d_in[6];
    const float* W4  = (const float*)d_in[7];
    const float* b4  = (const float*)d_in[8];
    const int*   act = (const int*)d_in[9];
    float* out = (float*)d_out;

    int B = in_sizes[0] / XDIM;

    static bool attr_set = false;
    if (!attr_set) {
        cudaFuncSetAttribute(k4_mlp, cudaFuncAttributeMaxDynamicSharedMemorySize, SMEM_TOTAL);
        attr_set = true;
    }

    int k4_blocks = (B + 3 * RPC) / RPC;

    k0_zero<<<1, 32>>>();
    k1_prep<<<(B + 7) / 8, 256>>>(x, act, out, B);
    k2_bases<<<1, 1>>>();
    k3_assign<<<(B + 255) / 256, 256>>>(act, B);
    k4_mlp<<<k4_blocks, 256, SMEM_TOTAL>>>(W1, b1, W2, b2, W3, b3, W4, b4, out);
}

// round 6
// speedup vs baseline: 5.9655x; 1.9200x over previous
#include <cuda_runtime.h>
#include <cuda_bf16.h>
#include <cstdint>

// Problem constants (fixed shapes)
#define XDIM 362
#define GRID_STRIDE 19
#define MAXB 65536
#define RPC 128                       // rows per CTA (M tile)
#define PERM_CAP (MAXB + 3*RPC)

// ---------------- device scratch ----------------
__device__ float g_att[MAXB * 8];
__device__ int   g_idx[MAXB * 8];
__device__ int   g_perm[PERM_CAP];
__device__ int   g_hist[3];
__device__ int   g_slot[3];
__device__ int   g_bases[3];
__device__ int   g_tp;

// pre-split weight planes (bf16 hi/lo), panel-ready layouts
// W2 planes: [A][112][400]  (k zero-padded 100->112)
// W3 planes: [A][400][112]  (n zero-padded 100->112)
#define W2P (3*112*400)
#define W3P (3*400*112)
__device__ __nv_bfloat16 g_w2h[W2P];
__device__ __nv_bfloat16 g_w2l[W2P];
__device__ __nv_bfloat16 g_w3h[W3P];
__device__ __nv_bfloat16 g_w3l[W3P];

// ---------------- small helpers ----------------
__device__ __forceinline__ int clampi(int v) {
    v = v < 1 ? 1 : v;
    return v > (XDIM - 1) ? (XDIM - 1) : v;
}
__device__ __forceinline__ uint32_t smem_u32(const void* p) {
    return (uint32_t)__cvta_generic_to_shared(p);
}
__device__ __forceinline__ void bsplit(float v, __nv_bfloat16& h, __nv_bfloat16& l) {
    h = __float2bfloat16_rn(v);
    l = __float2bfloat16_rn(v - __bfloat162float(h));
}
__device__ __forceinline__ uint32_t bf16bits(__nv_bfloat16 h) {
    __nv_bfloat16_raw r = static_cast<__nv_bfloat16_raw>(h);
    return (uint32_t)r.x;
}
__device__ __forceinline__ void cp_async16(void* smem, const void* gmem) {
    unsigned s = (unsigned)__cvta_generic_to_shared(smem);
    asm volatile("cp.async.cg.shared.global [%0], [%1], 16;\n" :: "r"(s), "l"(gmem));
}
__device__ __forceinline__ void cp_commit() { asm volatile("cp.async.commit_group;\n"); }
__device__ __forceinline__ void cp_wait_all() { asm volatile("cp.async.wait_group 0;\n"); }
__device__ __forceinline__ void barwg(int id) {
    asm volatile("bar.sync %0, 256;" :: "r"(id) : "memory");
}

// ---------------- mma / ldmatrix ----------------
__device__ __forceinline__ void mma16816(float* d, const uint32_t* a, const uint32_t* b) {
    asm volatile(
        "mma.sync.aligned.m16n8k16.row.col.f32.bf16.bf16.f32 "
        "{%0,%1,%2,%3}, {%4,%5,%6,%7}, {%8,%9}, {%0,%1,%2,%3};"
        : "+f"(d[0]), "+f"(d[1]), "+f"(d[2]), "+f"(d[3])
        : "r"(a[0]), "r"(a[1]), "r"(a[2]), "r"(a[3]), "r"(b[0]), "r"(b[1]));
}
__device__ __forceinline__ void ldmx4(uint32_t* r, uint32_t addr) {
    asm volatile("ldmatrix.sync.aligned.m8n8.x4.shared.b16 {%0,%1,%2,%3}, [%4];"
                 : "=r"(r[0]), "=r"(r[1]), "=r"(r[2]), "=r"(r[3]) : "r"(addr));
}
__device__ __forceinline__ void ldmx2t(uint32_t* r, uint32_t addr) {
    asm volatile("ldmatrix.sync.aligned.m8n8.x2.trans.shared.b16 {%0,%1}, [%2];"
                 : "=r"(r[0]), "=r"(r[1]) : "r"(addr));
}

// ---------------- K0 ----------------
__global__ void k0_zero() {
    if (threadIdx.x < 3) { g_hist[threadIdx.x] = 0; g_slot[threadIdx.x] = 0; }
}

// ---------------- K_wsplit: pre-split W2/W3 into bf16 hi/lo panel planes ----------
__global__ void k_wsplit(const float* __restrict__ W2, const float* __restrict__ W3) {
    int i = blockIdx.x * blockDim.x + threadIdx.x;
    if (i < W2P) {
        int a = i / (112 * 400);
        int rem = i % (112 * 400);
        int k = rem / 400, n = rem % 400;
        float v = (k < 100) ? W2[a * 40000 + k * 400 + n] : 0.f;
        __nv_bfloat16 h, l; bsplit(v, h, l);
        g_w2h[i] = h; g_w2l[i] = l;
    }
    if (i < W3P) {
        int a = i / (400 * 112);
        int rem = i % (400 * 112);
        int k = rem / 112, n = rem % 112;
        float v = (n < 100) ? W3[a * 40000 + k * 100 + n] : 0.f;
        __nv_bfloat16 h, l; bsplit(v, h, l);
        g_w3h[i] = h; g_w3l[i] = l;
    }
}

// ---------------- K1: copy x->out, argmax, gather, histogram ----------------
__global__ void k1_prep(const float* __restrict__ x, const int* __restrict__ act,
                        float* __restrict__ out, int B) {
    __shared__ int s_hist[3];
    if (threadIdx.x < 3) s_hist[threadIdx.x] = 0;
    __syncthreads();

    int warp = (blockIdx.x * blockDim.x + threadIdx.x) >> 5;
    int lane = threadIdx.x & 31;

    if (warp < B) {
        const float* xr = x + (size_t)warp * XDIM;
        float* outr = out + (size_t)warp * XDIM;
        float best = -3.402823466e+38f;
        int bidx = 0;
        for (int i = lane; i < XDIM; i += 32) {
            float v = xr[i];
            outr[i] = v;
            if (v > best) { best = v; bidx = i; }
        }
        #pragma unroll
        for (int off = 16; off; off >>= 1) {
            float ov = __shfl_xor_sync(0xffffffffu, best, off);
            int   oi = __shfl_xor_sync(0xffffffffu, bidx, off);
            if (ov > best || (ov == best && oi < bidx)) { best = ov; bidx = oi; }
        }
        if (lane == 0) {
            int ptr = bidx;
            int id[6];
            id[0] = 0;
            id[1] = ptr;                        // unclamped, as in source
            id[2] = clampi(ptr - GRID_STRIDE);
            id[3] = clampi(ptr + GRID_STRIDE);
            id[4] = clampi(ptr - 1);
            id[5] = clampi(ptr + 1);
            #pragma unroll
            for (int j = 0; j < 6; j++) {
                g_idx[warp * 8 + j] = id[j];
                g_att[warp * 8 + j] = xr[id[j]];
            }
            atomicAdd(&s_hist[act[warp]], 1);
        }
    }
    __syncthreads();
    if (threadIdx.x < 3) atomicAdd(&g_hist[threadIdx.x], s_hist[threadIdx.x]);
}

// ---------------- K2: bases padded to 128, pad slots -1 ----------------
__global__ void k2_bases() {
    int c0 = g_hist[0], c1 = g_hist[1], c2 = g_hist[2];
    int p1 = ((c0 + RPC - 1) / RPC) * RPC;
    int p2 = p1 + ((c1 + RPC - 1) / RPC) * RPC;
    int tp = p2 + ((c2 + RPC - 1) / RPC) * RPC;
    g_bases[0] = 0; g_bases[1] = p1; g_bases[2] = p2; g_tp = tp;
    for (int s = c0; s < p1; s++) g_perm[s] = -1;
    for (int s = p1 + c1; s < p2; s++) g_perm[s] = -1;
    for (int s = p2 + c2; s < tp; s++) g_perm[s] = -1;
}

// ---------------- K3: bucket assignment ----------------
__global__ void k3_assign(const int* __restrict__ act, int B) {
    int i = blockIdx.x * blockDim.x + threadIdx.x;
    int lane = threadIdx.x & 31;
    int a = (i < B) ? act[i] : -1;
    #pragma unroll
    for (int aa = 0; aa < 3; aa++) {
        unsigned m = __ballot_sync(0xffffffffu, a == aa);
        if (a == aa) {
            int leader = __ffs(m) - 1;
            int base = 0;
            if (lane == leader) base = atomicAdd(&g_slot[aa], __popc(m));
            base = __shfl_sync(m, base, leader);
            int off = __popc(m & ((1u << lane) - 1u));
            g_perm[g_bases[aa] + base + off] = i;
        }
    }
}

// ---------------- K4: fused MLP, 2 warpgroups, cp.async panels ----------------
#define KPAD2 120      // A2 row stride (bf16)
#define NPAD2 72       // B2 panel row stride (bf16), 144B
#define NPAD3 120      // B3 panel row stride (bf16), 240B
#define H3PAD 112

// per-wg panel block: B2H(16128) B2L(16128) B3H(15360) B3L(15360) = 62976 bytes
#define PNL_B2H 0
#define PNL_B2L 16128
#define PNL_B3H 32256
#define PNL_B3L 47616
#define PNL_SIZE 62976

#define OFF_A2H  0
#define OFF_A2L  30720
#define OFF_P0   61440
#define OFF_P1   124416
#define OFF_D3   124416          // aliases wg1 panels (57344 <= 62976)
#define OFF_B2S  187392          // 400 f
#define OFF_B3S  188992          // 100 f (pad to 448B)
#define OFF_W1S  189440          // 700 f
#define OFF_W4S  192240          // 608 f
#define OFF_ATT  194672          // 128*8 f
#define OFF_PRED 198768          // 128*6 f
#define OFF_IDX  201840          // 128*8 i
#define OFF_ROW  205936          // 128 i
#define SMEM_TOTAL 206448

__global__ void __launch_bounds__(512, 1)
k4_mlp(const float* __restrict__ W1, const float* __restrict__ b1,
       const float* __restrict__ b2, const float* __restrict__ b3,
       const float* __restrict__ W4, const float* __restrict__ b4,
       float* __restrict__ out) {
    extern __shared__ char smem[];
    const uint32_t sb = smem_u32(smem);

    __nv_bfloat16* a2h = (__nv_bfloat16*)(smem + OFF_A2H);
    __nv_bfloat16* a2l = (__nv_bfloat16*)(smem + OFF_A2L);
    float* s_d3   = (float*)(smem + OFF_D3);
    float* s_b2   = (float*)(smem + OFF_B2S);
    float* s_b3   = (float*)(smem + OFF_B3S);
    float* s_w1   = (float*)(smem + OFF_W1S);
    float* s_w4   = (float*)(smem + OFF_W4S);
    float* s_att  = (float*)(smem + OFF_ATT);
    float* s_pred = (float*)(smem + OFF_PRED);
    int*   s_idx  = (int*)(smem + OFF_IDX);
    int*   s_row  = (int*)(smem + OFF_ROW);

    const int t = threadIdx.x;
    const int lane = t & 31;
    const int wid = t >> 5;           // 0..15
    const int wgid = wid >> 3;        // warpgroup 0/1
    const int wl = wid & 7;           // m-strip within wg
    const int tw = t & 255;           // thread id within wg
    const int gid = lane >> 2;
    const int tid4 = lane & 3;
    const int gstart = blockIdx.x * RPC;
    if (gstart >= g_tp) return;
    const int a = (gstart >= g_bases[2]) ? 2 : (gstart >= g_bases[1]) ? 1 : 0;

    const uint32_t pnl = sb + ((wgid == 0) ? OFF_P0 : OFF_P1);
    __nv_bfloat16* pb = (__nv_bfloat16*)(smem + ((wgid == 0) ? OFF_P0 : OFF_P1));

    // ---- stage small params + row metadata, zero A2 pads ----
    for (int i = t; i < 600; i += 512) s_w1[i] = W1[a * 600 + i];
    for (int i = t; i < 100; i += 512) s_w1[600 + i] = b1[a * 100 + i];
    for (int i = t; i < 600; i += 512) s_w4[i] = W4[a * 600 + i];
    if (t < 6) s_w4[600 + t] = b4[a * 6 + t];
    for (int i = t; i < 400; i += 512) s_b2[i] = b2[a * 400 + i];
    for (int i = t; i < 100; i += 512) s_b3[i] = b3[a * 100 + i];
    for (int i = t; i < 128 * 20; i += 512) {
        int r = i / 20, c = 100 + i % 20;
        a2h[r * KPAD2 + c] = __float2bfloat16(0.f);
        a2l[r * KPAD2 + c] = __float2bfloat16(0.f);
    }
    if (t < RPC) {
        int row = g_perm[gstart + t];
        s_row[t] = row;
        if (row >= 0) {
            #pragma unroll
            for (int j = 0; j < 8; j++) {
                s_att[t * 8 + j] = g_att[row * 8 + j];
                s_idx[t * 8 + j] = g_idx[row * 8 + j];
            }
        } else {
            #pragma unroll
            for (int j = 0; j < 8; j++) { s_att[t * 8 + j] = 0.f; s_idx[t * 8 + j] = 0; }
        }
    }
    __syncthreads();

    // ---- layer 1 on cores: att[128,6] -> h1[128,100], split into A2 panels ----
    for (int o = t; o < RPC * 100; o += 512) {
        int r = o / 100, c = o % 100;
        float acc = s_w1[600 + c];
        #pragma unroll
        for (int k = 0; k < 6; k++) acc += s_att[r * 8 + k] * s_w1[k * 100 + c];
        float v = fmaxf(acc, 0.f);
        __nv_bfloat16 hb, lb; bsplit(v, hb, lb);
        a2h[r * KPAD2 + c] = hb;
        a2l[r * KPAD2 + c] = lb;
    }
    __syncthreads();

    // ---- fused layers 2+3: wg0 handles chunks 0,2,4,6; wg1 handles 1,3,5 ----
    float acc3[14][4];
    #pragma unroll
    for (int j = 0; j < 14; j++) { acc3[j][0]=0.f; acc3[j][1]=0.f; acc3[j][2]=0.f; acc3[j][3]=0.f; }

    const int mrow = 16 * wl;
    const __nv_bfloat16* w2hg = g_w2h + a * 112 * 400;
    const __nv_bfloat16* w2lg = g_w2l + a * 112 * 400;
    const __nv_bfloat16* w3hg = g_w3h + a * 400 * 112;
    const __nv_bfloat16* w3lg = g_w3l + a * 400 * 112;

    for (int c = wgid; c < 7; c += 2) {
        const int cbase = c * 64;
        const int width = (c < 6) ? 64 : 16;
        const int ntiles = width >> 3;
        const int nseg2 = width >> 3;      // 16B segments per B2 row

        // -- stage B2/B3 panels via cp.async from pre-split planes --
        for (int i = tw; i < 112 * nseg2; i += 256) {
            int k = i / nseg2, seg = i % nseg2;
            const __nv_bfloat16* s2h = w2hg + k * 400 + cbase + seg * 8;
            const __nv_bfloat16* s2l = w2lg + k * 400 + cbase + seg * 8;
            cp_async16(pb + (PNL_B2H/2) + k * NPAD2 + seg * 8, s2h);
            cp_async16(pb + (PNL_B2L/2) + k * NPAD2 + seg * 8, s2l);
        }
        for (int i = tw; i < width * 14; i += 256) {
            int kl = i / 14, seg = i % 14;
            const __nv_bfloat16* s3h = w3hg + (cbase + kl) * 112 + seg * 8;
            const __nv_bfloat16* s3l = w3lg + (cbase + kl) * 112 + seg * 8;
            cp_async16(pb + (PNL_B3H/2) + kl * NPAD3 + seg * 8, s3h);
            cp_async16(pb + (PNL_B3L/2) + kl * NPAD3 + seg * 8, s3l);
        }
        cp_commit();
        cp_wait_all();
        barwg(1 + wgid);

        // -- layer 2 chunk: acc2[ntiles][4] over K2=112 (7 ksteps) --
        float acc2[8][4];
        #pragma unroll
        for (int j = 0; j < 8; j++) {
            if (j < ntiles) {
                float bv0 = s_b2[cbase + 8 * j + tid4 * 2];
                float bv1 = s_b2[cbase + 8 * j + tid4 * 2 + 1];
                acc2[j][0] = bv0; acc2[j][1] = bv1; acc2[j][2] = bv0; acc2[j][3] = bv1;
            }
        }
        const uint32_t arow = (uint32_t)(mrow + (lane & 15));
        const uint32_t acolofs = (uint32_t)((lane >> 4) << 3);
        #pragma unroll
        for (int ks = 0; ks < 7; ks++) {
            uint32_t ah[4], al[4];
            uint32_t acol = (uint32_t)(ks * 16) + acolofs;
            ldmx4(ah, sb + OFF_A2H + (arow * KPAD2 + acol) * 2);
            ldmx4(al, sb + OFF_A2L + (arow * KPAD2 + acol) * 2);
            const uint32_t krow = (uint32_t)(ks * 16 + (lane & 15));
            for (int j = 0; j < ntiles; j++) {
                uint32_t bh[2], bl[2];
                uint32_t boff = (krow * NPAD2 + (uint32_t)(j * 8)) * 2;
                ldmx2t(bh, pnl + PNL_B2H + boff);
                ldmx2t(bl, pnl + PNL_B2L + boff);
                mma16816(acc2[j], ah, bh);
                mma16816(acc2[j], ah, bl);
                mma16816(acc2[j], al, bh);
            }
        }

        // -- relu + bf16-split in registers -> A3 frags; layer 3 accumulate --
        const int ksteps3 = ntiles >> 1;
        for (int g = 0; g < ksteps3; g++) {
            float v0, v1;
            uint32_t a3h[4], a3l[4];
            __nv_bfloat16 h0, l0, h1, l1;
            v0 = fmaxf(acc2[2*g][0], 0.f);   v1 = fmaxf(acc2[2*g][1], 0.f);
            bsplit(v0, h0, l0); bsplit(v1, h1, l1);
            a3h[0] = bf16bits(h0) | (bf16bits(h1) << 16);
            a3l[0] = bf16bits(l0) | (bf16bits(l1) << 16);
            v0 = fmaxf(acc2[2*g][2], 0.f);   v1 = fmaxf(acc2[2*g][3], 0.f);
            bsplit(v0, h0, l0); bsplit(v1, h1, l1);
            a3h[1] = bf16bits(h0) | (bf16bits(h1) << 16);
            a3l[1] = bf16bits(l0) | (bf16bits(l1) << 16);
            v0 = fmaxf(acc2[2*g+1][0], 0.f); v1 = fmaxf(acc2[2*g+1][1], 0.f);
            bsplit(v0, h0, l0); bsplit(v1, h1, l1);
            a3h[2] = bf16bits(h0) | (bf16bits(h1) << 16);
            a3l[2] = bf16bits(l0) | (bf16bits(l1) << 16);
            v0 = fmaxf(acc2[2*g+1][2], 0.f); v1 = fmaxf(acc2[2*g+1][3], 0.f);
            bsplit(v0, h0, l0); bsplit(v1, h1, l1);
            a3h[3] = bf16bits(h0) | (bf16bits(h1) << 16);
            a3l[3] = bf16bits(l0) | (bf16bits(l1) << 16);

            const uint32_t krow3 = (uint32_t)(g * 16 + (lane & 15));
            #pragma unroll
            for (int j3 = 0; j3 < 14; j3++) {
                uint32_t bh[2], bl[2];
                uint32_t boff = (krow3 * NPAD3 + (uint32_t)(j3 * 8)) * 2;
                ldmx2t(bh, pnl + PNL_B3H + boff);
                ldmx2t(bl, pnl + PNL_B3L + boff);
                mma16816(acc3[j3], a3h, bh);
                mma16816(acc3[j3], a3h, bl);
                mma16816(acc3[j3], a3l, bh);
            }
        }
        barwg(1 + wgid);   // panel reads done before next stage overwrites
    }

    // ---- cross-warpgroup reduction of d3, bias, relu -> s_d3 (h3 layout) ----
    // wg1 writes its partial d3 (aliases its own dead panel buffer)
    if (wgid == 1) {
        #pragma unroll
        for (int j = 0; j < 14; j++) {
            #pragma unroll
            for (int q = 0; q < 4; q++) {
                int n = 8 * j + tid4 * 2 + (q & 1);
                int row = mrow + gid + ((q >= 2) ? 8 : 0);
                s_d3[row * H3PAD + n] = acc3[j][q];
            }
        }
    }
    __syncthreads();
    if (wgid == 0) {
        #pragma unroll
        for (int j = 0; j < 14; j++) {
            #pragma unroll
            for (int q = 0; q < 4; q++) {
                int n = 8 * j + tid4 * 2 + (q & 1);
                int row = mrow + gid + ((q >= 2) ? 8 : 0);
                float bias = (n < 100) ? s_b3[n] : 0.f;
                float v = acc3[j][q] + s_d3[row * H3PAD + n] + bias;
                s_d3[row * H3PAD + n] = fmaxf(v, 0.f);
            }
        }
    }
    __syncthreads();

    // ---- layer 4 on cores: h3[128,100] -> pred[128,6] ----
    for (int o = t; o < RPC * 6; o += 512) {
        int r = o / 6, cc = o % 6;
        float acc = s_w4[600 + cc];
        #pragma unroll 4
        for (int k = 0; k < 100; k++) acc += s_d3[r * H3PAD + k] * s_w4[k * 6 + cc];
        s_pred[o] = acc;
    }
    __syncthreads();

    // ---- scatter ----
    if (t < RPC) {
        int row = s_row[t];
        if (row >= 0) {
            float* o = out + (size_t)row * XDIM;
            #pragma unroll
            for (int j = 0; j < 6; j++)
                o[s_idx[t * 8 + j]] = s_att[t * 8 + j] + s_pred[t * 6 + j];
        }
    }
}

// ---------------- launch ----------------
extern "C" void kernel_launch(void* const* d_in, const int* in_sizes, int n_in,
                              void* d_out, int out_size) {
    const float* x   = (const float*)d_in[0];
    const float* W1  = (const float*)d_in[1];
    const float* b1  = (const float*)d_in[2];
    const float* W2  = (const float*)d_in[3];
    const float* b2  = (const float*)d_in[4];
    const float* W3  = (const float*)d_in[5];
    const float* b3  = (const float*)d_in[6];
    const float* W4  = (const float*)d_in[7];
    const float* b4  = (const float*)d_in[8];
    const int*   act = (const int*)d_in[9];
    float* out = (float*)d_out;

    int B = in_sizes[0] / XDIM;

    static bool attr_set = false;
    if (!attr_set) {
        cudaFuncSetAttribute(k4_mlp, cudaFuncAttributeMaxDynamicSharedMemorySize, SMEM_TOTAL);
        attr_set = true;
    }

    int k4_blocks = (B + 3 * RPC) / RPC;

    k0_zero<<<1, 32>>>();
    k_wsplit<<<(W2P + 255) / 256, 256>>>(W2, W3);
    k1_prep<<<(B + 7) / 8, 256>>>(x, act, out, B);
    k2_bases<<<1, 1>>>();
    k3_assign<<<(B + 255) / 256, 256>>>(act, B);
    k4_mlp<<<k4_blocks, 512, SMEM_TOTAL>>>(W1, b1, b2, b3, W4, b4, out);
}

// round 7
// speedup vs baseline: 6.3461x; 1.0638x over previous
#include <cuda_runtime.h>
#include <cuda_bf16.h>
#include <cstdint>

// Problem constants (fixed shapes)
#define XDIM 362
#define GRID_STRIDE 19
#define MAXB 65536
#define RPC 128                       // rows per CTA (M tile)

// ---------------- device scratch ----------------
__device__ float g_att[MAXB * 8];
__device__ int   g_idx[MAXB * 8];
__device__ int   g_perm[3 * MAXB];    // fixed per-action regions
__device__ int   g_slot[3];           // per-action counts (append cursors)
__device__ int   g_blkb[4];           // per-action block bases (in K4 blocks)

// pre-split weight planes (bf16 hi/lo), panel-ready layouts
// W2 planes: [A][112][400]  (k zero-padded 100->112)
// W3 planes: [A][400][112]  (n zero-padded 100->112)
#define W2P (3*112*400)
#define W3P (3*400*112)
__device__ __nv_bfloat16 g_w2h[W2P];
__device__ __nv_bfloat16 g_w2l[W2P];
__device__ __nv_bfloat16 g_w3h[W3P];
__device__ __nv_bfloat16 g_w3l[W3P];

// ---------------- small helpers ----------------
__device__ __forceinline__ int clampi(int v) {
    v = v < 1 ? 1 : v;
    return v > (XDIM - 1) ? (XDIM - 1) : v;
}
__device__ __forceinline__ uint32_t smem_u32(const void* p) {
    return (uint32_t)__cvta_generic_to_shared(p);
}
__device__ __forceinline__ void bsplit(float v, __nv_bfloat16& h, __nv_bfloat16& l) {
    h = __float2bfloat16_rn(v);
    l = __float2bfloat16_rn(v - __bfloat162float(h));
}
__device__ __forceinline__ uint32_t bf16bits(__nv_bfloat16 h) {
    __nv_bfloat16_raw r = static_cast<__nv_bfloat16_raw>(h);
    return (uint32_t)r.x;
}
__device__ __forceinline__ void cp_async16(void* smem, const void* gmem) {
    unsigned s = (unsigned)__cvta_generic_to_shared(smem);
    asm volatile("cp.async.cg.shared.global [%0], [%1], 16;\n" :: "r"(s), "l"(gmem));
}
__device__ __forceinline__ void cp_commit() { asm volatile("cp.async.commit_group;\n"); }
__device__ __forceinline__ void cp_wait_all() { asm volatile("cp.async.wait_group 0;\n"); }
__device__ __forceinline__ void barwg(int id) {
    asm volatile("bar.sync %0, 256;" :: "r"(id) : "memory");
}

// ---------------- mma / ldmatrix ----------------
__device__ __forceinline__ void mma16816(float* d, const uint32_t* a, const uint32_t* b) {
    asm volatile(
        "mma.sync.aligned.m16n8k16.row.col.f32.bf16.bf16.f32 "
        "{%0,%1,%2,%3}, {%4,%5,%6,%7}, {%8,%9}, {%0,%1,%2,%3};"
        : "+f"(d[0]), "+f"(d[1]), "+f"(d[2]), "+f"(d[3])
        : "r"(a[0]), "r"(a[1]), "r"(a[2]), "r"(a[3]), "r"(b[0]), "r"(b[1]));
}
__device__ __forceinline__ void ldmx4(uint32_t* r, uint32_t addr) {
    asm volatile("ldmatrix.sync.aligned.m8n8.x4.shared.b16 {%0,%1,%2,%3}, [%4];"
                 : "=r"(r[0]), "=r"(r[1]), "=r"(r[2]), "=r"(r[3]) : "r"(addr));
}
// x4 trans: lanes 0-7 rows of mat0, 8-15 mat1, 16-23 mat2, 24-31 mat3
// -> regs {b0lo,b0hi,b1lo,b1hi} = fragments for TWO adjacent n-tiles
__device__ __forceinline__ void ldmx4t(uint32_t* r, uint32_t addr) {
    asm volatile("ldmatrix.sync.aligned.m8n8.x4.trans.shared.b16 {%0,%1,%2,%3}, [%4];"
                 : "=r"(r[0]), "=r"(r[1]), "=r"(r[2]), "=r"(r[3]) : "r"(addr));
}

// ---------------- K_wsplit: pre-split W2/W3 + zero cursors ----------------
__global__ void k_wsplit(const float* __restrict__ W2, const float* __restrict__ W3) {
    int i = blockIdx.x * blockDim.x + threadIdx.x;
    if (i < 3) g_slot[i] = 0;
    if (i < W2P) {
        int a = i / (112 * 400);
        int rem = i % (112 * 400);
        int k = rem / 400, n = rem % 400;
        float v = (k < 100) ? W2[a * 40000 + k * 400 + n] : 0.f;
        __nv_bfloat16 h, l; bsplit(v, h, l);
        g_w2h[i] = h; g_w2l[i] = l;
    }
    if (i < W3P) {
        int a = i / (400 * 112);
        int rem = i % (400 * 112);
        int k = rem / 112, n = rem % 112;
        float v = (n < 100) ? W3[a * 40000 + k * 100 + n] : 0.f;
        __nv_bfloat16 h, l; bsplit(v, h, l);
        g_w3h[i] = h; g_w3l[i] = l;
    }
}

// ---------------- K1: copy x->out, argmax, gather, direct bucket append -------
__global__ void k1_prep(const float* __restrict__ x, const int* __restrict__ act,
                        float* __restrict__ out, int B) {
    __shared__ int s_cnt[3];
    __shared__ int s_base[3];
    __shared__ int s_local[8];     // per-warp local slot
    __shared__ int s_act[8];
    if (threadIdx.x < 3) s_cnt[threadIdx.x] = 0;
    __syncthreads();

    int warp = (blockIdx.x * blockDim.x + threadIdx.x) >> 5;
    int wl = (threadIdx.x >> 5);
    int lane = threadIdx.x & 31;

    if (warp < B) {
        const float* xr = x + (size_t)warp * XDIM;
        float* outr = out + (size_t)warp * XDIM;
        float best = -3.402823466e+38f;
        int bidx = 0;
        for (int i = lane; i < XDIM; i += 32) {
            float v = xr[i];
            outr[i] = v;
            if (v > best) { best = v; bidx = i; }
        }
        #pragma unroll
        for (int off = 16; off; off >>= 1) {
            float ov = __shfl_xor_sync(0xffffffffu, best, off);
            int   oi = __shfl_xor_sync(0xffffffffu, bidx, off);
            if (ov > best || (ov == best && oi < bidx)) { best = ov; bidx = oi; }
        }
        if (lane == 0) {
            int ptr = bidx;
            int id[6];
            id[0] = 0;
            id[1] = ptr;                        // unclamped, as in source
            id[2] = clampi(ptr - GRID_STRIDE);
            id[3] = clampi(ptr + GRID_STRIDE);
            id[4] = clampi(ptr - 1);
            id[5] = clampi(ptr + 1);
            #pragma unroll
            for (int j = 0; j < 6; j++) {
                g_idx[warp * 8 + j] = id[j];
                g_att[warp * 8 + j] = xr[id[j]];
            }
            int a = act[warp];
            s_act[wl] = a;
            s_local[wl] = atomicAdd(&s_cnt[a], 1);
        }
    }
    __syncthreads();
    if (threadIdx.x < 3 && s_cnt[threadIdx.x] > 0)
        s_base[threadIdx.x] = atomicAdd(&g_slot[threadIdx.x], s_cnt[threadIdx.x]);
    __syncthreads();
    if (warp < B && lane == 0) {
        int a = s_act[wl];
        g_perm[a * MAXB + s_base[a] + s_local[wl]] = warp;
    }
}

// ---------------- K2: per-action block bases ----------------
__global__ void k2_bases() {
    if (threadIdx.x == 0) {
        int nb0 = (g_slot[0] + RPC - 1) / RPC;
        int nb1 = (g_slot[1] + RPC - 1) / RPC;
        int nb2 = (g_slot[2] + RPC - 1) / RPC;
        g_blkb[0] = 0;
        g_blkb[1] = nb0;
        g_blkb[2] = nb0 + nb1;
        g_blkb[3] = nb0 + nb1 + nb2;
    }
}

// ---------------- K4: fused MLP, 2 warpgroups, cp.async panels ----------------
#define KPAD2 120      // A2 row stride (bf16)
#define NPAD2 72       // B2 panel row stride (bf16), 144B
#define NPAD3 120      // B3 panel row stride (bf16), 240B
#define H3PAD 112

// per-wg panel block: B2H(16128) B2L(16128) B3H(15360) B3L(15360) = 62976 bytes
#define PNL_B2H 0
#define PNL_B2L 16128
#define PNL_B3H 32256
#define PNL_B3L 47616

#define OFF_A2H  0
#define OFF_A2L  30720
#define OFF_P0   61440
#define OFF_P1   124416
#define OFF_D3   124416          // aliases wg1 panels (57344 <= 62976)
#define OFF_B2S  187392          // 400 f
#define OFF_B3S  188992          // 100 f (pad to 448B)
#define OFF_W1S  189440          // 700 f
#define OFF_W4S  192240          // 608 f
#define OFF_ATT  194672          // 128*8 f
#define OFF_PRED 198768          // 128*6 f
#define OFF_IDX  201840          // 128*8 i
#define OFF_ROW  205936          // 128 i
#define SMEM_TOTAL 206448

__global__ void __launch_bounds__(512, 1)
k4_mlp(const float* __restrict__ W1, const float* __restrict__ b1,
       const float* __restrict__ b2, const float* __restrict__ b3,
       const float* __restrict__ W4, const float* __restrict__ b4,
       float* __restrict__ out) {
    const int bid = blockIdx.x;
    if (bid >= g_blkb[3]) return;
    extern __shared__ char smem[];
    const uint32_t sb = smem_u32(smem);

    __nv_bfloat16* a2h = (__nv_bfloat16*)(smem + OFF_A2H);
    __nv_bfloat16* a2l = (__nv_bfloat16*)(smem + OFF_A2L);
    float* s_d3   = (float*)(smem + OFF_D3);
    float* s_b2   = (float*)(smem + OFF_B2S);
    float* s_b3   = (float*)(smem + OFF_B3S);
    float* s_w1   = (float*)(smem + OFF_W1S);
    float* s_w4   = (float*)(smem + OFF_W4S);
    float* s_att  = (float*)(smem + OFF_ATT);
    float* s_pred = (float*)(smem + OFF_PRED);
    int*   s_idx  = (int*)(smem + OFF_IDX);
    int*   s_row  = (int*)(smem + OFF_ROW);

    const int t = threadIdx.x;
    const int lane = t & 31;
    const int wid = t >> 5;           // 0..15
    const int wgid = wid >> 3;        // warpgroup 0/1
    const int wl = wid & 7;           // m-strip within wg
    const int tw = t & 255;           // thread id within wg
    const int gid = lane >> 2;
    const int tid4 = lane & 3;

    const int a = (bid >= g_blkb[2]) ? 2 : (bid >= g_blkb[1]) ? 1 : 0;
    const int lstart = (bid - g_blkb[a]) * RPC;
    const int cnt = g_slot[a];

    const uint32_t pnl = sb + ((wgid == 0) ? OFF_P0 : OFF_P1);
    __nv_bfloat16* pb = (__nv_bfloat16*)(smem + ((wgid == 0) ? OFF_P0 : OFF_P1));

    // ---- stage small params + row metadata, zero A2 pads ----
    for (int i = t; i < 600; i += 512) s_w1[i] = W1[a * 600 + i];
    for (int i = t; i < 100; i += 512) s_w1[600 + i] = b1[a * 100 + i];
    for (int i = t; i < 600; i += 512) s_w4[i] = W4[a * 600 + i];
    if (t < 6) s_w4[600 + t] = b4[a * 6 + t];
    for (int i = t; i < 400; i += 512) s_b2[i] = b2[a * 400 + i];
    for (int i = t; i < 100; i += 512) s_b3[i] = b3[a * 100 + i];
    for (int i = t; i < 128 * 20; i += 512) {
        int r = i / 20, c = 100 + i % 20;
        a2h[r * KPAD2 + c] = __float2bfloat16(0.f);
        a2l[r * KPAD2 + c] = __float2bfloat16(0.f);
    }
    if (t < RPC) {
        int row = (lstart + t < cnt) ? g_perm[a * MAXB + lstart + t] : -1;
        s_row[t] = row;
        if (row >= 0) {
            #pragma unroll
            for (int j = 0; j < 8; j++) {
                s_att[t * 8 + j] = g_att[row * 8 + j];
                s_idx[t * 8 + j] = g_idx[row * 8 + j];
            }
        } else {
            #pragma unroll
            for (int j = 0; j < 8; j++) { s_att[t * 8 + j] = 0.f; s_idx[t * 8 + j] = 0; }
        }
    }
    __syncthreads();

    // ---- layer 1 on cores: att[128,6] -> h1[128,100], split into A2 panels ----
    for (int o = t; o < RPC * 100; o += 512) {
        int r = o / 100, c = o % 100;
        float acc = s_w1[600 + c];
        #pragma unroll
        for (int k = 0; k < 6; k++) acc += s_att[r * 8 + k] * s_w1[k * 100 + c];
        float v = fmaxf(acc, 0.f);
        __nv_bfloat16 hb, lb; bsplit(v, hb, lb);
        a2h[r * KPAD2 + c] = hb;
        a2l[r * KPAD2 + c] = lb;
    }
    __syncthreads();

    // ---- fused layers 2+3: wg0 handles chunks 0,2,4,6; wg1 handles 1,3,5 ----
    float acc3[14][4];
    #pragma unroll
    for (int j = 0; j < 14; j++) { acc3[j][0]=0.f; acc3[j][1]=0.f; acc3[j][2]=0.f; acc3[j][3]=0.f; }

    const int mrow = 16 * wl;
    const __nv_bfloat16* w2hg = g_w2h + a * 112 * 400;
    const __nv_bfloat16* w2lg = g_w2l + a * 112 * 400;
    const __nv_bfloat16* w3hg = g_w3h + a * 400 * 112;
    const __nv_bfloat16* w3lg = g_w3l + a * 400 * 112;

    // per-lane n-offset for x4-trans B loads (lanes>=16 address the +8-col matrices)
    const uint32_t nofs = (uint32_t)((lane & 16) >> 1);   // 0 or 8

    for (int c = wgid; c < 7; c += 2) {
        const int cbase = c * 64;
        const int width = (c < 6) ? 64 : 16;
        const int ntiles = width >> 3;
        const int npairs = ntiles >> 1;
        const int nseg2 = width >> 3;      // 16B segments per B2 row

        // -- stage B2/B3 panels via cp.async from pre-split planes --
        for (int i = tw; i < 112 * nseg2; i += 256) {
            int k = i / nseg2, seg = i % nseg2;
            const __nv_bfloat16* s2h = w2hg + k * 400 + cbase + seg * 8;
            const __nv_bfloat16* s2l = w2lg + k * 400 + cbase + seg * 8;
            cp_async16(pb + (PNL_B2H/2) + k * NPAD2 + seg * 8, s2h);
            cp_async16(pb + (PNL_B2L/2) + k * NPAD2 + seg * 8, s2l);
        }
        for (int i = tw; i < width * 14; i += 256) {
            int kl = i / 14, seg = i % 14;
            const __nv_bfloat16* s3h = w3hg + (cbase + kl) * 112 + seg * 8;
            const __nv_bfloat16* s3l = w3lg + (cbase + kl) * 112 + seg * 8;
            cp_async16(pb + (PNL_B3H/2) + kl * NPAD3 + seg * 8, s3h);
            cp_async16(pb + (PNL_B3L/2) + kl * NPAD3 + seg * 8, s3l);
        }
        cp_commit();
        cp_wait_all();
        barwg(1 + wgid);

        // -- layer 2 chunk: acc2[ntiles][4] over K2=112 (7 ksteps) --
        float acc2[8][4];
        #pragma unroll
        for (int j = 0; j < 8; j++) {
            if (j < ntiles) {
                float bv0 = s_b2[cbase + 8 * j + tid4 * 2];
                float bv1 = s_b2[cbase + 8 * j + tid4 * 2 + 1];
                acc2[j][0] = bv0; acc2[j][1] = bv1; acc2[j][2] = bv0; acc2[j][3] = bv1;
            }
        }
        const uint32_t arow = (uint32_t)(mrow + (lane & 15));
        const uint32_t acolofs = (uint32_t)((lane >> 4) << 3);
        #pragma unroll
        for (int ks = 0; ks < 7; ks++) {
            uint32_t ah[4], al[4];
            uint32_t acol = (uint32_t)(ks * 16) + acolofs;
            ldmx4(ah, sb + OFF_A2H + (arow * KPAD2 + acol) * 2);
            ldmx4(al, sb + OFF_A2L + (arow * KPAD2 + acol) * 2);
            const uint32_t krow = (uint32_t)(ks * 16 + (lane & 15));
            for (int jp = 0; jp < npairs; jp++) {
                uint32_t bh[4], bl[4];
                uint32_t boff = (krow * NPAD2 + (uint32_t)(jp * 16) + nofs) * 2;
                ldmx4t(bh, pnl + PNL_B2H + boff);
                ldmx4t(bl, pnl + PNL_B2L + boff);
                mma16816(acc2[2*jp],   ah, bh);
                mma16816(acc2[2*jp],   ah, bl);
                mma16816(acc2[2*jp],   al, bh);
                mma16816(acc2[2*jp+1], ah, bh + 2);
                mma16816(acc2[2*jp+1], ah, bl + 2);
                mma16816(acc2[2*jp+1], al, bh + 2);
            }
        }

        // -- relu + bf16-split in registers -> A3 frags; layer 3 accumulate --
        const int ksteps3 = ntiles >> 1;
        for (int g = 0; g < ksteps3; g++) {
            float v0, v1;
            uint32_t a3h[4], a3l[4];
            __nv_bfloat16 h0, l0, h1, l1;
            v0 = fmaxf(acc2[2*g][0], 0.f);   v1 = fmaxf(acc2[2*g][1], 0.f);
            bsplit(v0, h0, l0); bsplit(v1, h1, l1);
            a3h[0] = bf16bits(h0) | (bf16bits(h1) << 16);
            a3l[0] = bf16bits(l0) | (bf16bits(l1) << 16);
            v0 = fmaxf(acc2[2*g][2], 0.f);   v1 = fmaxf(acc2[2*g][3], 0.f);
            bsplit(v0, h0, l0); bsplit(v1, h1, l1);
            a3h[1] = bf16bits(h0) | (bf16bits(h1) << 16);
            a3l[1] = bf16bits(l0) | (bf16bits(l1) << 16);
            v0 = fmaxf(acc2[2*g+1][0], 0.f); v1 = fmaxf(acc2[2*g+1][1], 0.f);
            bsplit(v0, h0, l0); bsplit(v1, h1, l1);
            a3h[2] = bf16bits(h0) | (bf16bits(h1) << 16);
            a3l[2] = bf16bits(l0) | (bf16bits(l1) << 16);
            v0 = fmaxf(acc2[2*g+1][2], 0.f); v1 = fmaxf(acc2[2*g+1][3], 0.f);
            bsplit(v0, h0, l0); bsplit(v1, h1, l1);
            a3h[3] = bf16bits(h0) | (bf16bits(h1) << 16);
            a3l[3] = bf16bits(l0) | (bf16bits(l1) << 16);

            const uint32_t krow3 = (uint32_t)(g * 16 + (lane & 15));
            #pragma unroll
            for (int jp3 = 0; jp3 < 7; jp3++) {
                uint32_t bh[4], bl[4];
                uint32_t boff = (krow3 * NPAD3 + (uint32_t)(jp3 * 16) + nofs) * 2;
                ldmx4t(bh, pnl + PNL_B3H + boff);
                ldmx4t(bl, pnl + PNL_B3L + boff);
                mma16816(acc3[2*jp3],   a3h, bh);
                mma16816(acc3[2*jp3],   a3h, bl);
                mma16816(acc3[2*jp3],   a3l, bh);
                mma16816(acc3[2*jp3+1], a3h, bh + 2);
                mma16816(acc3[2*jp3+1], a3h, bl + 2);
                mma16816(acc3[2*jp3+1], a3l, bh + 2);
            }
        }
        barwg(1 + wgid);   // panel reads done before next stage overwrites
    }

    // ---- cross-warpgroup reduction of d3, bias, relu -> s_d3 (h3 layout) ----
    if (wgid == 1) {
        #pragma unroll
        for (int j = 0; j < 14; j++) {
            #pragma unroll
            for (int q = 0; q < 4; q++) {
                int n = 8 * j + tid4 * 2 + (q & 1);
                int row = mrow + gid + ((q >= 2) ? 8 : 0);
                s_d3[row * H3PAD + n] = acc3[j][q];
            }
        }
    }
    __syncthreads();
    if (wgid == 0) {
        #pragma unroll
        for (int j = 0; j < 14; j++) {
            #pragma unroll
            for (int q = 0; q < 4; q++) {
                int n = 8 * j + tid4 * 2 + (q & 1);
                int row = mrow + gid + ((q >= 2) ? 8 : 0);
                float bias = (n < 100) ? s_b3[n] : 0.f;
                float v = acc3[j][q] + s_d3[row * H3PAD + n] + bias;
                s_d3[row * H3PAD + n] = fmaxf(v, 0.f);
            }
        }
    }
    __syncthreads();

    // ---- layer 4 on cores: h3[128,100] -> pred[128,6] ----
    for (int o = t; o < RPC * 6; o += 512) {
        int r = o / 6, cc = o % 6;
        float acc = s_w4[600 + cc];
        #pragma unroll 4
        for (int k = 0; k < 100; k++) acc += s_d3[r * H3PAD + k] * s_w4[k * 6 + cc];
        s_pred[o] = acc;
    }
    __syncthreads();

    // ---- scatter ----
    if (t < RPC) {
        int row = s_row[t];
        if (row >= 0) {
            float* o = out + (size_t)row * XDIM;
            #pragma unroll
            for (int j = 0; j < 6; j++)
                o[s_idx[t * 8 + j]] = s_att[t * 8 + j] + s_pred[t * 6 + j];
        }
    }
}

// ---------------- launch ----------------
extern "C" void kernel_launch(void* const* d_in, const int* in_sizes, int n_in,
                              void* d_out, int out_size) {
    const float* x   = (const float*)d_in[0];
    const float* W1  = (const float*)d_in[1];
    const float* b1  = (const float*)d_in[2];
    const float* W2  = (const float*)d_in[3];
    const float* b2  = (const float*)d_in[4];
    const float* W3  = (const float*)d_in[5];
    const float* b3  = (const float*)d_in[6];
    const float* W4  = (const float*)d_in[7];
    const float* b4  = (const float*)d_in[8];
    const int*   act = (const int*)d_in[9];
    float* out = (float*)d_out;

    int B = in_sizes[0] / XDIM;

    static bool attr_set = false;
    if (!attr_set) {
        cudaFuncSetAttribute(k4_mlp, cudaFuncAttributeMaxDynamicSharedMemorySize, SMEM_TOTAL);
        attr_set = true;
    }

    int k4_blocks = (B + RPC - 1) / RPC + 3;   // >= sum of per-action block counts

    k_wsplit<<<(W2P + 255) / 256, 256>>>(W2, W3);
    k1_prep<<<(B + 7) / 8, 256>>>(x, act, out, B);
    k2_bases<<<1, 32>>>();
    k4_mlp<<<k4_blocks, 512, SMEM_TOTAL>>>(W1, b1, b2, b3, W4, b4, out);
}